// round 4
// baseline (speedup 1.0000x reference)
#include <cuda_runtime.h>
#include <cuda_bf16.h>
#include <cstdint>

#define N_NODES 50000
#define E_ORIG  800000
#define E_TOT   850000   // E_ORIG + N self-loops
#define FULLMASK 0xffffffffu

// ---------------- scratch (static __device__ — no allocation) ----------------
__device__ __align__(16) int   g_src32[E_TOT];
__device__ __align__(16) int   g_dst32[E_TOT];
__device__ __align__(16) int   g_srcs [E_TOT];        // src sorted by dst (CSR)
__device__ __align__(16) int   g_deg[N_NODES];
__device__ __align__(16) int   g_rowstart[N_NODES + 1];
__device__ __align__(16) int   g_cursor[N_NODES];
__device__ __align__(16) float g_h1  [N_NODES * 128]; // x @ W1
__device__ __align__(16) float g_as1 [N_NODES * 4];
__device__ __align__(16) float g_ad1 [N_NODES * 4];
__device__ __align__(16) float g_out1[N_NODES * 128]; // relu(agg1 + b1)
__device__ __align__(16) float g_h2  [N_NODES * 64];  // out1 @ W2
__device__ __align__(16) float g_as2 [N_NODES];
__device__ __align__(16) float g_ad2 [N_NODES];

__device__ __forceinline__ float lrelu(float v) {
    return v > 0.f ? v : 0.2f * v;
}

// ---------------- CSR build ----------------
__global__ void zero_deg_kernel() {
    int i = blockIdx.x * blockDim.x + threadIdx.x;
    if (i < N_NODES) g_deg[i] = 0;
}

// edge_index is INT32 (JAX default x64-disabled downcasts int64 -> int32)
__global__ void build_edges_kernel(const int* __restrict__ ei) {
    int e = blockIdx.x * blockDim.x + threadIdx.x;
    if (e >= E_TOT) return;
    int s, d;
    if (e < E_ORIG) {
        s = ei[e];
        d = ei[E_ORIG + e];
    } else {
        s = d = e - E_ORIG;   // self loop
    }
    g_src32[e] = s;
    g_dst32[e] = d;
    if ((unsigned)d < (unsigned)N_NODES)   // guard wild atomics (dtype safety)
        atomicAdd(&g_deg[d], 1);
}

// single-block exclusive scan of g_deg -> g_rowstart, g_cursor
__global__ void scan_kernel() {
    __shared__ int warpoff[32];
    __shared__ int warpsum[32];
    __shared__ int s_carry;
    int tid = threadIdx.x, lane = tid & 31, wid = tid >> 5;
    if (tid == 0) s_carry = 0;
    __syncthreads();
    for (int base = 0; base < N_NODES; base += 1024) {
        int i = base + tid;
        int v = (i < N_NODES) ? g_deg[i] : 0;
        int x = v;
        #pragma unroll
        for (int off = 1; off < 32; off <<= 1) {
            int t = __shfl_up_sync(FULLMASK, x, off);
            if (lane >= off) x += t;
        }
        if (lane == 31) warpsum[wid] = x;
        __syncthreads();
        if (wid == 0) {
            int s = warpsum[lane];
            int y = s;
            #pragma unroll
            for (int off = 1; off < 32; off <<= 1) {
                int t = __shfl_up_sync(FULLMASK, y, off);
                if (lane >= off) y += t;
            }
            warpoff[lane] = y - s;  // exclusive among warps
        }
        __syncthreads();
        int carry = s_carry;
        int excl = carry + warpoff[wid] + (x - v);
        if (i < N_NODES) { g_rowstart[i] = excl; g_cursor[i] = excl; }
        __syncthreads();
        if (tid == 1023) s_carry = carry + warpoff[31] + x;  // chunk total
        __syncthreads();
    }
    if (threadIdx.x == 0) g_rowstart[N_NODES] = s_carry;
}

__global__ void scatter_kernel() {
    int e = blockIdx.x * blockDim.x + threadIdx.x;
    if (e >= E_TOT) return;
    int d = g_dst32[e];
    if ((unsigned)d >= (unsigned)N_NODES) return;
    int pos = atomicAdd(&g_cursor[d], 1);
    if ((unsigned)pos < (unsigned)E_TOT)
        g_srcs[pos] = g_src32[e];
}

// ---------------- GEMM1: h1[N,128] = x[N,128] @ W1[128,128] ----------------
__global__ __launch_bounds__(256) void gemm1_kernel(const float* __restrict__ X,
                                                    const float* __restrict__ W) {
    __shared__ __align__(16) float As[16][132];
    __shared__ __align__(16) float Bs[16][128];
    int tid = threadIdx.x;
    int tx = tid & 15, ty = tid >> 4;
    int blockRow = blockIdx.x * 128;
    float acc[8][8];
    #pragma unroll
    for (int i = 0; i < 8; i++)
        #pragma unroll
        for (int j = 0; j < 8; j++) acc[i][j] = 0.f;

    for (int k0 = 0; k0 < 128; k0 += 16) {
        #pragma unroll
        for (int l = 0; l < 2; l++) {
            int id = tid * 2 + l;            // 0..511
            int r = id >> 2, c4 = (id & 3) * 4;
            int grow = blockRow + r;
            float4 v = make_float4(0.f, 0.f, 0.f, 0.f);
            if (grow < N_NODES) v = *(const float4*)&X[grow * 128 + k0 + c4];
            As[c4 + 0][r] = v.x; As[c4 + 1][r] = v.y;
            As[c4 + 2][r] = v.z; As[c4 + 3][r] = v.w;
        }
        #pragma unroll
        for (int l = 0; l < 2; l++) {
            int id = tid * 2 + l;            // 0..511
            int r = id >> 5, c4 = (id & 31) * 4;
            *(float4*)&Bs[r][c4] = *(const float4*)&W[(k0 + r) * 128 + c4];
        }
        __syncthreads();
        #pragma unroll
        for (int k = 0; k < 16; k++) {
            float a[8], b[8];
            *(float4*)&a[0] = *(const float4*)&As[k][ty * 4];
            *(float4*)&a[4] = *(const float4*)&As[k][64 + ty * 4];
            *(float4*)&b[0] = *(const float4*)&Bs[k][tx * 4];
            *(float4*)&b[4] = *(const float4*)&Bs[k][64 + tx * 4];
            #pragma unroll
            for (int i = 0; i < 8; i++)
                #pragma unroll
                for (int j = 0; j < 8; j++)
                    acc[i][j] = fmaf(a[i], b[j], acc[i][j]);
        }
        __syncthreads();
    }
    #pragma unroll
    for (int i = 0; i < 8; i++) {
        int gr = blockRow + ((i < 4) ? (ty * 4 + i) : (64 + ty * 4 + i - 4));
        if (gr < N_NODES) {
            *(float4*)&g_h1[gr * 128 + tx * 4] =
                make_float4(acc[i][0], acc[i][1], acc[i][2], acc[i][3]);
            *(float4*)&g_h1[gr * 128 + 64 + tx * 4] =
                make_float4(acc[i][4], acc[i][5], acc[i][6], acc[i][7]);
        }
    }
}

// ---------------- alpha projections layer 1 ----------------
__global__ void alpha1_kernel(const float* __restrict__ a_src,
                              const float* __restrict__ a_dst) {
    int n = blockIdx.x;
    int t = threadIdx.x;             // 128
    float v = g_h1[n * 128 + t];
    float ps = v * a_src[t];
    float pd = v * a_dst[t];
    #pragma unroll
    for (int off = 16; off >= 1; off >>= 1) {
        ps += __shfl_xor_sync(FULLMASK, ps, off);
        pd += __shfl_xor_sync(FULLMASK, pd, off);
    }
    if ((t & 31) == 0) {
        g_as1[n * 4 + (t >> 5)] = ps;
        g_ad1[n * 4 + (t >> 5)] = pd;
    }
}

// ---------------- layer-1 aggregation: warp per dst node ----------------
__global__ __launch_bounds__(256) void agg1_kernel(const float* __restrict__ b1) {
    int warpid = threadIdx.x >> 5;
    int lane = threadIdx.x & 31;
    int n = blockIdx.x * 8 + warpid;
    if (n >= N_NODES) return;
    int s0 = g_rowstart[n], s1 = g_rowstart[n + 1];
    float4 ad = *(const float4*)&g_ad1[n * 4];

    // phase A: per-head max
    float m0 = -1e30f, m1 = -1e30f, m2 = -1e30f, m3 = -1e30f;
    for (int e = s0 + lane; e < s1; e += 32) {
        int s = g_srcs[e];
        float4 a = *(const float4*)&g_as1[s * 4];
        m0 = fmaxf(m0, lrelu(a.x + ad.x));
        m1 = fmaxf(m1, lrelu(a.y + ad.y));
        m2 = fmaxf(m2, lrelu(a.z + ad.z));
        m3 = fmaxf(m3, lrelu(a.w + ad.w));
    }
    #pragma unroll
    for (int off = 16; off >= 1; off >>= 1) {
        m0 = fmaxf(m0, __shfl_xor_sync(FULLMASK, m0, off));
        m1 = fmaxf(m1, __shfl_xor_sync(FULLMASK, m1, off));
        m2 = fmaxf(m2, __shfl_xor_sync(FULLMASK, m2, off));
        m3 = fmaxf(m3, __shfl_xor_sync(FULLMASK, m3, off));
    }
    // phase B: denom
    float d0 = 0.f, d1 = 0.f, d2 = 0.f, d3 = 0.f;
    for (int e = s0 + lane; e < s1; e += 32) {
        int s = g_srcs[e];
        float4 a = *(const float4*)&g_as1[s * 4];
        d0 += __expf(lrelu(a.x + ad.x) - m0);
        d1 += __expf(lrelu(a.y + ad.y) - m1);
        d2 += __expf(lrelu(a.z + ad.z) - m2);
        d3 += __expf(lrelu(a.w + ad.w) - m3);
    }
    #pragma unroll
    for (int off = 16; off >= 1; off >>= 1) {
        d0 += __shfl_xor_sync(FULLMASK, d0, off);
        d1 += __shfl_xor_sync(FULLMASK, d1, off);
        d2 += __shfl_xor_sync(FULLMASK, d2, off);
        d3 += __shfl_xor_sync(FULLMASK, d3, off);
    }
    float r0 = 1.f / d0, r1 = 1.f / d1, r2 = 1.f / d2, r3 = 1.f / d3;

    // phase C: weighted accumulate, chunked 32 edges at a time
    float acc0 = 0.f, acc1 = 0.f, acc2 = 0.f, acc3 = 0.f;
    for (int base = s0; base < s1; base += 32) {
        int e = base + lane;
        int cnt = min(32, s1 - base);
        int sl = 0;
        float w0 = 0.f, w1 = 0.f, w2 = 0.f, w3 = 0.f;
        if (e < s1) {
            sl = g_srcs[e];
            float4 a = *(const float4*)&g_as1[sl * 4];
            w0 = __expf(lrelu(a.x + ad.x) - m0) * r0;
            w1 = __expf(lrelu(a.y + ad.y) - m1) * r1;
            w2 = __expf(lrelu(a.z + ad.z) - m2) * r2;
            w3 = __expf(lrelu(a.w + ad.w) - m3) * r3;
        }
        for (int j = 0; j < cnt; j++) {
            int s  = __shfl_sync(FULLMASK, sl, j);
            float x0 = __shfl_sync(FULLMASK, w0, j);
            float x1 = __shfl_sync(FULLMASK, w1, j);
            float x2 = __shfl_sync(FULLMASK, w2, j);
            float x3 = __shfl_sync(FULLMASK, w3, j);
            const float* hp = g_h1 + s * 128 + lane;
            acc0 = fmaf(hp[0],  x0, acc0);
            acc1 = fmaf(hp[32], x1, acc1);
            acc2 = fmaf(hp[64], x2, acc2);
            acc3 = fmaf(hp[96], x3, acc3);
        }
    }
    int o = n * 128 + lane;
    g_out1[o]      = fmaxf(acc0 + b1[lane],      0.f);
    g_out1[o + 32] = fmaxf(acc1 + b1[lane + 32], 0.f);
    g_out1[o + 64] = fmaxf(acc2 + b1[lane + 64], 0.f);
    g_out1[o + 96] = fmaxf(acc3 + b1[lane + 96], 0.f);
}

// ---------------- GEMM2: h2[N,64] = out1[N,128] @ W2[128,64] ----------------
__global__ __launch_bounds__(256) void gemm2_kernel(const float* __restrict__ W) {
    __shared__ __align__(16) float As[16][132];
    __shared__ __align__(16) float Bs[16][64];
    int tid = threadIdx.x;
    int tx = tid & 15, ty = tid >> 4;
    int blockRow = blockIdx.x * 128;
    float acc[8][4];
    #pragma unroll
    for (int i = 0; i < 8; i++)
        #pragma unroll
        for (int j = 0; j < 4; j++) acc[i][j] = 0.f;

    for (int k0 = 0; k0 < 128; k0 += 16) {
        #pragma unroll
        for (int l = 0; l < 2; l++) {
            int id = tid * 2 + l;
            int r = id >> 2, c4 = (id & 3) * 4;
            int grow = blockRow + r;
            float4 v = make_float4(0.f, 0.f, 0.f, 0.f);
            if (grow < N_NODES) v = *(const float4*)&g_out1[grow * 128 + k0 + c4];
            As[c4 + 0][r] = v.x; As[c4 + 1][r] = v.y;
            As[c4 + 2][r] = v.z; As[c4 + 3][r] = v.w;
        }
        if (tid < 256) {
            int r = tid >> 4, c4 = (tid & 15) * 4;   // 16 rows x 16 float4
            *(float4*)&Bs[r][c4] = *(const float4*)&W[(k0 + r) * 64 + c4];
        }
        __syncthreads();
        #pragma unroll
        for (int k = 0; k < 16; k++) {
            float a[8], b[4];
            *(float4*)&a[0] = *(const float4*)&As[k][ty * 4];
            *(float4*)&a[4] = *(const float4*)&As[k][64 + ty * 4];
            *(float4*)&b[0] = *(const float4*)&Bs[k][tx * 4];
            #pragma unroll
            for (int i = 0; i < 8; i++)
                #pragma unroll
                for (int j = 0; j < 4; j++)
                    acc[i][j] = fmaf(a[i], b[j], acc[i][j]);
        }
        __syncthreads();
    }
    #pragma unroll
    for (int i = 0; i < 8; i++) {
        int gr = blockRow + ((i < 4) ? (ty * 4 + i) : (64 + ty * 4 + i - 4));
        if (gr < N_NODES)
            *(float4*)&g_h2[gr * 64 + tx * 4] =
                make_float4(acc[i][0], acc[i][1], acc[i][2], acc[i][3]);
    }
}

// ---------------- alpha projections layer 2 (H=1, C=64) ----------------
__global__ void alpha2_kernel(const float* __restrict__ a_src,
                              const float* __restrict__ a_dst) {
    int lane = threadIdx.x & 31;
    int n = blockIdx.x * 8 + (threadIdx.x >> 5);
    if (n >= N_NODES) return;
    float v0 = g_h2[n * 64 + lane];
    float v1 = g_h2[n * 64 + 32 + lane];
    float ps = v0 * a_src[lane] + v1 * a_src[32 + lane];
    float pd = v0 * a_dst[lane] + v1 * a_dst[32 + lane];
    #pragma unroll
    for (int off = 16; off >= 1; off >>= 1) {
        ps += __shfl_xor_sync(FULLMASK, ps, off);
        pd += __shfl_xor_sync(FULLMASK, pd, off);
    }
    if (lane == 0) { g_as2[n] = ps; g_ad2[n] = pd; }
}

// ---------------- layer-2 aggregation: warp per dst node -> d_out ----------------
__global__ __launch_bounds__(256) void agg2_kernel(const float* __restrict__ b2,
                                                   float* __restrict__ out) {
    int warpid = threadIdx.x >> 5;
    int lane = threadIdx.x & 31;
    int n = blockIdx.x * 8 + warpid;
    if (n >= N_NODES) return;
    int s0 = g_rowstart[n], s1 = g_rowstart[n + 1];
    float ad = g_ad2[n];

    float m = -1e30f;
    for (int e = s0 + lane; e < s1; e += 32)
        m = fmaxf(m, lrelu(g_as2[g_srcs[e]] + ad));
    #pragma unroll
    for (int off = 16; off >= 1; off >>= 1)
        m = fmaxf(m, __shfl_xor_sync(FULLMASK, m, off));

    float d = 0.f;
    for (int e = s0 + lane; e < s1; e += 32)
        d += __expf(lrelu(g_as2[g_srcs[e]] + ad) - m);
    #pragma unroll
    for (int off = 16; off >= 1; off >>= 1)
        d += __shfl_xor_sync(FULLMASK, d, off);
    float rd = 1.f / d;

    float acc0 = 0.f, acc1 = 0.f;
    for (int base = s0; base < s1; base += 32) {
        int e = base + lane;
        int cnt = min(32, s1 - base);
        int sl = 0;
        float w = 0.f;
        if (e < s1) {
            sl = g_srcs[e];
            w = __expf(lrelu(g_as2[sl] + ad) - m) * rd;
        }
        for (int j = 0; j < cnt; j++) {
            int s  = __shfl_sync(FULLMASK, sl, j);
            float x = __shfl_sync(FULLMASK, w, j);
            const float* hp = g_h2 + s * 64 + lane;
            acc0 = fmaf(hp[0],  x, acc0);
            acc1 = fmaf(hp[32], x, acc1);
        }
    }
    out[n * 64 + lane]      = acc0 + b2[lane];
    out[n * 64 + 32 + lane] = acc1 + b2[32 + lane];
}

// ---------------- launcher ----------------
extern "C" void kernel_launch(void* const* d_in, const int* in_sizes, int n_in,
                              void* d_out, int out_size) {
    const float* x      = (const float*)d_in[0];
    const int*   ei     = (const int*)d_in[1];   // int32 (JAX x64 disabled)
    // d_in[2] edge_weight unused (PyG GATConv ignores it with edge_dim unset)
    const float* W1     = (const float*)d_in[3];
    const float* a_src1 = (const float*)d_in[4];
    const float* a_dst1 = (const float*)d_in[5];
    const float* b1     = (const float*)d_in[6];
    const float* W2     = (const float*)d_in[7];
    const float* a_src2 = (const float*)d_in[8];
    const float* a_dst2 = (const float*)d_in[9];
    const float* b2     = (const float*)d_in[10];
    float*       out    = (float*)d_out;

    zero_deg_kernel<<<(N_NODES + 255) / 256, 256>>>();
    build_edges_kernel<<<(E_TOT + 255) / 256, 256>>>(ei);
    scan_kernel<<<1, 1024>>>();
    scatter_kernel<<<(E_TOT + 255) / 256, 256>>>();

    gemm1_kernel<<<(N_NODES + 127) / 128, 256>>>(x, W1);
    alpha1_kernel<<<N_NODES, 128>>>(a_src1, a_dst1);
    agg1_kernel<<<(N_NODES + 7) / 8, 256>>>(b1);

    gemm2_kernel<<<(N_NODES + 127) / 128, 256>>>(W2);
    alpha2_kernel<<<(N_NODES + 7) / 8, 256>>>(a_src2, a_dst2);
    agg2_kernel<<<(N_NODES + 7) / 8, 256>>>(b2, out);
}

// round 5
// speedup vs baseline: 1.1641x; 1.1641x over previous
#include <cuda_runtime.h>
#include <cuda_bf16.h>
#include <cstdint>

#define N_NODES 50000
#define E_ORIG  800000
#define E_TOT   850000   // E_ORIG + N self-loops (both divisible by 4)
#define FULLMASK 0xffffffffu

// ---------------- scratch (static __device__ — no allocation) ----------------
__device__ __align__(16) int   g_src32[E_TOT];
__device__ __align__(16) int   g_dst32[E_TOT];
__device__ __align__(16) int   g_srcs [E_TOT];        // src sorted by dst (CSR)
__device__ __align__(16) int   g_deg[N_NODES];
__device__ __align__(16) int   g_rowstart[N_NODES + 1];
__device__ __align__(16) int   g_cursor[N_NODES];
__device__ __align__(16) float g_h1  [N_NODES * 128]; // x @ W1
__device__ __align__(16) float g_as1 [N_NODES * 4];
__device__ __align__(16) float g_ad1 [N_NODES * 4];
__device__ __align__(16) float g_out1[N_NODES * 128]; // relu(agg1 + b1)
__device__ __align__(16) float g_h2  [N_NODES * 64];  // out1 @ W2
__device__ __align__(16) float g_as2 [N_NODES];
__device__ __align__(16) float g_ad2 [N_NODES];

__device__ __forceinline__ float lrelu(float v) {
    return v > 0.f ? v : 0.2f * v;
}

// packed f32x2 helpers (FFMA2 — ptxas never emits it from C++)
__device__ __forceinline__ unsigned long long pack_dup(float a) {
    unsigned long long r;
    asm("mov.b64 %0, {%1, %1};" : "=l"(r) : "f"(a));
    return r;
}
__device__ __forceinline__ void ffma2(unsigned long long& acc,
                                      unsigned long long a,
                                      unsigned long long b) {
    asm("fma.rn.f32x2 %0, %1, %2, %0;" : "+l"(acc) : "l"(a), "l"(b));
}
__device__ __forceinline__ float2 unpack2(unsigned long long v) {
    float lo, hi;
    asm("mov.b64 {%0, %1}, %2;" : "=f"(lo), "=f"(hi) : "l"(v));
    return make_float2(lo, hi);
}

// ---------------- CSR build ----------------
// edge_index is INT32 (JAX x64 disabled downcasts int64 -> int32)
__global__ void build_edges_kernel(const int* __restrict__ ei) {
    int e = (blockIdx.x * blockDim.x + threadIdx.x) * 4;
    if (e >= E_TOT) return;
    int4 s4, d4;
    if (e < E_ORIG) {                       // E_ORIG % 4 == 0: no straddle
        s4 = *(const int4*)&ei[e];
        d4 = *(const int4*)&ei[E_ORIG + e];
    } else {
        int b = e - E_ORIG;
        s4 = make_int4(b, b + 1, b + 2, b + 3);
        d4 = s4;
    }
    *(int4*)&g_src32[e] = s4;
    *(int4*)&g_dst32[e] = d4;
    if ((unsigned)d4.x < (unsigned)N_NODES) atomicAdd(&g_deg[d4.x], 1);
    if ((unsigned)d4.y < (unsigned)N_NODES) atomicAdd(&g_deg[d4.y], 1);
    if ((unsigned)d4.z < (unsigned)N_NODES) atomicAdd(&g_deg[d4.z], 1);
    if ((unsigned)d4.w < (unsigned)N_NODES) atomicAdd(&g_deg[d4.w], 1);
}

// single-block exclusive scan of g_deg -> g_rowstart, g_cursor
__global__ void scan_kernel() {
    __shared__ int warpoff[32];
    __shared__ int warpsum[32];
    __shared__ int s_carry;
    int tid = threadIdx.x, lane = tid & 31, wid = tid >> 5;
    if (tid == 0) s_carry = 0;
    __syncthreads();
    for (int base = 0; base < N_NODES; base += 1024) {
        int i = base + tid;
        int v = (i < N_NODES) ? g_deg[i] : 0;
        int x = v;
        #pragma unroll
        for (int off = 1; off < 32; off <<= 1) {
            int t = __shfl_up_sync(FULLMASK, x, off);
            if (lane >= off) x += t;
        }
        if (lane == 31) warpsum[wid] = x;
        __syncthreads();
        if (wid == 0) {
            int s = warpsum[lane];
            int y = s;
            #pragma unroll
            for (int off = 1; off < 32; off <<= 1) {
                int t = __shfl_up_sync(FULLMASK, y, off);
                if (lane >= off) y += t;
            }
            warpoff[lane] = y - s;  // exclusive among warps
        }
        __syncthreads();
        int carry = s_carry;
        int excl = carry + warpoff[wid] + (x - v);
        if (i < N_NODES) { g_rowstart[i] = excl; g_cursor[i] = excl; }
        __syncthreads();
        if (tid == 1023) s_carry = carry + warpoff[31] + x;  // chunk total
        __syncthreads();
    }
    if (threadIdx.x == 0) g_rowstart[N_NODES] = s_carry;
}

__global__ void scatter_kernel() {
    int e = (blockIdx.x * blockDim.x + threadIdx.x) * 4;
    if (e >= E_TOT) return;
    int4 d4 = *(const int4*)&g_dst32[e];
    int4 s4 = *(const int4*)&g_src32[e];
    #pragma unroll
    for (int l = 0; l < 4; l++) {
        int d = (l == 0) ? d4.x : (l == 1) ? d4.y : (l == 2) ? d4.z : d4.w;
        int s = (l == 0) ? s4.x : (l == 1) ? s4.y : (l == 2) ? s4.z : s4.w;
        if ((unsigned)d < (unsigned)N_NODES) {
            int pos = atomicAdd(&g_cursor[d], 1);
            if ((unsigned)pos < (unsigned)E_TOT) g_srcs[pos] = s;
        }
    }
}

// ---------------- GEMM1: h1[N,128] = x[N,128] @ W1[128,128] (FFMA2) --------
__global__ __launch_bounds__(256) void gemm1_kernel(const float* __restrict__ X,
                                                    const float* __restrict__ W) {
    __shared__ __align__(16) float As[16][132];
    __shared__ __align__(16) float Bs[16][128];
    int tid = threadIdx.x;
    int tx = tid & 15, ty = tid >> 4;
    int blockRow = blockIdx.x * 128;
    unsigned long long accp[8][4];
    #pragma unroll
    for (int i = 0; i < 8; i++)
        #pragma unroll
        for (int j = 0; j < 4; j++) accp[i][j] = 0ull;

    for (int k0 = 0; k0 < 128; k0 += 16) {
        #pragma unroll
        for (int l = 0; l < 2; l++) {
            int id = tid * 2 + l;            // 0..511
            int r = id >> 2, c4 = (id & 3) * 4;
            int grow = blockRow + r;
            float4 v = make_float4(0.f, 0.f, 0.f, 0.f);
            if (grow < N_NODES) v = *(const float4*)&X[grow * 128 + k0 + c4];
            As[c4 + 0][r] = v.x; As[c4 + 1][r] = v.y;
            As[c4 + 2][r] = v.z; As[c4 + 3][r] = v.w;
        }
        #pragma unroll
        for (int l = 0; l < 2; l++) {
            int id = tid * 2 + l;            // 0..511
            int r = id >> 5, c4 = (id & 31) * 4;
            *(float4*)&Bs[r][c4] = *(const float4*)&W[(k0 + r) * 128 + c4];
        }
        __syncthreads();
        #pragma unroll
        for (int k = 0; k < 16; k++) {
            float a[8];
            *(float4*)&a[0] = *(const float4*)&As[k][ty * 4];
            *(float4*)&a[4] = *(const float4*)&As[k][64 + ty * 4];
            unsigned long long bp[4];
            bp[0] = *(const unsigned long long*)&Bs[k][tx * 4];
            bp[1] = *(const unsigned long long*)&Bs[k][tx * 4 + 2];
            bp[2] = *(const unsigned long long*)&Bs[k][64 + tx * 4];
            bp[3] = *(const unsigned long long*)&Bs[k][64 + tx * 4 + 2];
            #pragma unroll
            for (int i = 0; i < 8; i++) {
                unsigned long long ap = pack_dup(a[i]);
                #pragma unroll
                for (int j = 0; j < 4; j++) ffma2(accp[i][j], ap, bp[j]);
            }
        }
        __syncthreads();
    }
    #pragma unroll
    for (int i = 0; i < 8; i++) {
        int gr = blockRow + ((i < 4) ? (ty * 4 + i) : (64 + ty * 4 + i - 4));
        if (gr < N_NODES) {
            float2 p0 = unpack2(accp[i][0]), p1 = unpack2(accp[i][1]);
            float2 p2 = unpack2(accp[i][2]), p3 = unpack2(accp[i][3]);
            *(float4*)&g_h1[gr * 128 + tx * 4] = make_float4(p0.x, p0.y, p1.x, p1.y);
            *(float4*)&g_h1[gr * 128 + 64 + tx * 4] = make_float4(p2.x, p2.y, p3.x, p3.y);
        }
    }
}

// ---------------- alpha projections layer 1 ----------------
__global__ void alpha1_kernel(const float* __restrict__ a_src,
                              const float* __restrict__ a_dst) {
    int n = blockIdx.x;
    int t = threadIdx.x;             // 128
    float v = g_h1[n * 128 + t];
    float ps = v * a_src[t];
    float pd = v * a_dst[t];
    #pragma unroll
    for (int off = 16; off >= 1; off >>= 1) {
        ps += __shfl_xor_sync(FULLMASK, ps, off);
        pd += __shfl_xor_sync(FULLMASK, pd, off);
    }
    if ((t & 31) == 0) {
        g_as1[n * 4 + (t >> 5)] = ps;
        g_ad1[n * 4 + (t >> 5)] = pd;
    }
}

// ---------------- layer-1 aggregation: warp per dst node, online softmax ----
__global__ __launch_bounds__(256) void agg1_kernel(const float* __restrict__ b1) {
    int warpid = threadIdx.x >> 5;
    int lane = threadIdx.x & 31;
    int n = blockIdx.x * 8 + warpid;
    if (n >= N_NODES) return;
    int s0 = g_rowstart[n], s1 = g_rowstart[n + 1];
    float4 ad = *(const float4*)&g_ad1[n * 4];

    // fused max+denom (online softmax, lane-local then warp combine)
    float m0 = -1e30f, m1 = -1e30f, m2 = -1e30f, m3 = -1e30f;
    float d0 = 0.f, d1 = 0.f, d2 = 0.f, d3 = 0.f;
    for (int e = s0 + lane; e < s1; e += 32) {
        int s = g_srcs[e];
        float4 a = *(const float4*)&g_as1[s * 4];
        float e0 = lrelu(a.x + ad.x), e1 = lrelu(a.y + ad.y);
        float e2 = lrelu(a.z + ad.z), e3 = lrelu(a.w + ad.w);
        float nm;
        nm = fmaxf(m0, e0); d0 = d0 * __expf(m0 - nm) + __expf(e0 - nm); m0 = nm;
        nm = fmaxf(m1, e1); d1 = d1 * __expf(m1 - nm) + __expf(e1 - nm); m1 = nm;
        nm = fmaxf(m2, e2); d2 = d2 * __expf(m2 - nm) + __expf(e2 - nm); m2 = nm;
        nm = fmaxf(m3, e3); d3 = d3 * __expf(m3 - nm) + __expf(e3 - nm); m3 = nm;
    }
    #pragma unroll
    for (int off = 16; off >= 1; off >>= 1) {
        float om, od, nm;
        om = __shfl_xor_sync(FULLMASK, m0, off); od = __shfl_xor_sync(FULLMASK, d0, off);
        nm = fmaxf(m0, om); d0 = d0 * __expf(m0 - nm) + od * __expf(om - nm); m0 = nm;
        om = __shfl_xor_sync(FULLMASK, m1, off); od = __shfl_xor_sync(FULLMASK, d1, off);
        nm = fmaxf(m1, om); d1 = d1 * __expf(m1 - nm) + od * __expf(om - nm); m1 = nm;
        om = __shfl_xor_sync(FULLMASK, m2, off); od = __shfl_xor_sync(FULLMASK, d2, off);
        nm = fmaxf(m2, om); d2 = d2 * __expf(m2 - nm) + od * __expf(om - nm); m2 = nm;
        om = __shfl_xor_sync(FULLMASK, m3, off); od = __shfl_xor_sync(FULLMASK, d3, off);
        nm = fmaxf(m3, om); d3 = d3 * __expf(m3 - nm) + od * __expf(om - nm); m3 = nm;
    }
    float r0 = 1.f / d0, r1 = 1.f / d1, r2 = 1.f / d2, r3 = 1.f / d3;

    // weighted accumulate, chunked 32 edges at a time
    float acc0 = 0.f, acc1 = 0.f, acc2 = 0.f, acc3 = 0.f;
    for (int base = s0; base < s1; base += 32) {
        int e = base + lane;
        int cnt = min(32, s1 - base);
        int sl = 0;
        float w0 = 0.f, w1 = 0.f, w2 = 0.f, w3 = 0.f;
        if (e < s1) {
            sl = g_srcs[e];
            float4 a = *(const float4*)&g_as1[sl * 4];
            w0 = __expf(lrelu(a.x + ad.x) - m0) * r0;
            w1 = __expf(lrelu(a.y + ad.y) - m1) * r1;
            w2 = __expf(lrelu(a.z + ad.z) - m2) * r2;
            w3 = __expf(lrelu(a.w + ad.w) - m3) * r3;
        }
        for (int j = 0; j < cnt; j++) {
            int s  = __shfl_sync(FULLMASK, sl, j);
            float x0 = __shfl_sync(FULLMASK, w0, j);
            float x1 = __shfl_sync(FULLMASK, w1, j);
            float x2 = __shfl_sync(FULLMASK, w2, j);
            float x3 = __shfl_sync(FULLMASK, w3, j);
            const float* hp = g_h1 + s * 128 + lane;
            acc0 = fmaf(hp[0],  x0, acc0);
            acc1 = fmaf(hp[32], x1, acc1);
            acc2 = fmaf(hp[64], x2, acc2);
            acc3 = fmaf(hp[96], x3, acc3);
        }
    }
    int o = n * 128 + lane;
    g_out1[o]      = fmaxf(acc0 + b1[lane],      0.f);
    g_out1[o + 32] = fmaxf(acc1 + b1[lane + 32], 0.f);
    g_out1[o + 64] = fmaxf(acc2 + b1[lane + 64], 0.f);
    g_out1[o + 96] = fmaxf(acc3 + b1[lane + 96], 0.f);
}

// ---------------- GEMM2: h2[N,64] = out1[N,128] @ W2[128,64] (FFMA2) -------
__global__ __launch_bounds__(256) void gemm2_kernel(const float* __restrict__ W) {
    __shared__ __align__(16) float As[16][132];
    __shared__ __align__(16) float Bs[16][64];
    int tid = threadIdx.x;
    int tx = tid & 15, ty = tid >> 4;
    int blockRow = blockIdx.x * 128;
    unsigned long long accp[8][2];
    #pragma unroll
    for (int i = 0; i < 8; i++) { accp[i][0] = 0ull; accp[i][1] = 0ull; }

    for (int k0 = 0; k0 < 128; k0 += 16) {
        #pragma unroll
        for (int l = 0; l < 2; l++) {
            int id = tid * 2 + l;
            int r = id >> 2, c4 = (id & 3) * 4;
            int grow = blockRow + r;
            float4 v = make_float4(0.f, 0.f, 0.f, 0.f);
            if (grow < N_NODES) v = *(const float4*)&g_out1[grow * 128 + k0 + c4];
            As[c4 + 0][r] = v.x; As[c4 + 1][r] = v.y;
            As[c4 + 2][r] = v.z; As[c4 + 3][r] = v.w;
        }
        {
            int r = tid >> 4, c4 = (tid & 15) * 4;   // 16 rows x 16 float4
            *(float4*)&Bs[r][c4] = *(const float4*)&W[(k0 + r) * 64 + c4];
        }
        __syncthreads();
        #pragma unroll
        for (int k = 0; k < 16; k++) {
            float a[8];
            *(float4*)&a[0] = *(const float4*)&As[k][ty * 4];
            *(float4*)&a[4] = *(const float4*)&As[k][64 + ty * 4];
            unsigned long long bp[2];
            bp[0] = *(const unsigned long long*)&Bs[k][tx * 4];
            bp[1] = *(const unsigned long long*)&Bs[k][tx * 4 + 2];
            #pragma unroll
            for (int i = 0; i < 8; i++) {
                unsigned long long ap = pack_dup(a[i]);
                ffma2(accp[i][0], ap, bp[0]);
                ffma2(accp[i][1], ap, bp[1]);
            }
        }
        __syncthreads();
    }
    #pragma unroll
    for (int i = 0; i < 8; i++) {
        int gr = blockRow + ((i < 4) ? (ty * 4 + i) : (64 + ty * 4 + i - 4));
        if (gr < N_NODES) {
            float2 p0 = unpack2(accp[i][0]), p1 = unpack2(accp[i][1]);
            *(float4*)&g_h2[gr * 64 + tx * 4] = make_float4(p0.x, p0.y, p1.x, p1.y);
        }
    }
}

// ---------------- alpha projections layer 2 (H=1, C=64) ----------------
__global__ void alpha2_kernel(const float* __restrict__ a_src,
                              const float* __restrict__ a_dst) {
    int lane = threadIdx.x & 31;
    int n = blockIdx.x * 8 + (threadIdx.x >> 5);
    if (n >= N_NODES) return;
    float v0 = g_h2[n * 64 + lane];
    float v1 = g_h2[n * 64 + 32 + lane];
    float ps = v0 * a_src[lane] + v1 * a_src[32 + lane];
    float pd = v0 * a_dst[lane] + v1 * a_dst[32 + lane];
    #pragma unroll
    for (int off = 16; off >= 1; off >>= 1) {
        ps += __shfl_xor_sync(FULLMASK, ps, off);
        pd += __shfl_xor_sync(FULLMASK, pd, off);
    }
    if (lane == 0) { g_as2[n] = ps; g_ad2[n] = pd; }
}

// ---------------- layer-2 aggregation: warp per dst node -> d_out ----------
__global__ __launch_bounds__(256) void agg2_kernel(const float* __restrict__ b2,
                                                   float* __restrict__ out) {
    int warpid = threadIdx.x >> 5;
    int lane = threadIdx.x & 31;
    int n = blockIdx.x * 8 + warpid;
    if (n >= N_NODES) return;
    int s0 = g_rowstart[n], s1 = g_rowstart[n + 1];
    float ad = g_ad2[n];

    float m = -1e30f, d = 0.f;
    for (int e = s0 + lane; e < s1; e += 32) {
        float ev = lrelu(g_as2[g_srcs[e]] + ad);
        float nm = fmaxf(m, ev);
        d = d * __expf(m - nm) + __expf(ev - nm);
        m = nm;
    }
    #pragma unroll
    for (int off = 16; off >= 1; off >>= 1) {
        float om = __shfl_xor_sync(FULLMASK, m, off);
        float od = __shfl_xor_sync(FULLMASK, d, off);
        float nm = fmaxf(m, om);
        d = d * __expf(m - nm) + od * __expf(om - nm);
        m = nm;
    }
    float rd = 1.f / d;

    float acc0 = 0.f, acc1 = 0.f;
    for (int base = s0; base < s1; base += 32) {
        int e = base + lane;
        int cnt = min(32, s1 - base);
        int sl = 0;
        float w = 0.f;
        if (e < s1) {
            sl = g_srcs[e];
            w = __expf(lrelu(g_as2[sl] + ad) - m) * rd;
        }
        for (int j = 0; j < cnt; j++) {
            int s  = __shfl_sync(FULLMASK, sl, j);
            float x = __shfl_sync(FULLMASK, w, j);
            const float* hp = g_h2 + s * 64 + lane;
            acc0 = fmaf(hp[0],  x, acc0);
            acc1 = fmaf(hp[32], x, acc1);
        }
    }
    out[n * 64 + lane]      = acc0 + b2[lane];
    out[n * 64 + 32 + lane] = acc1 + b2[32 + lane];
}

// ---------------- launcher ----------------
extern "C" void kernel_launch(void* const* d_in, const int* in_sizes, int n_in,
                              void* d_out, int out_size) {
    const float* x      = (const float*)d_in[0];
    const int*   ei     = (const int*)d_in[1];   // int32 (JAX x64 disabled)
    // d_in[2] edge_weight unused (PyG GATConv ignores it with edge_dim unset)
    const float* W1     = (const float*)d_in[3];
    const float* a_src1 = (const float*)d_in[4];
    const float* a_dst1 = (const float*)d_in[5];
    const float* b1     = (const float*)d_in[6];
    const float* W2     = (const float*)d_in[7];
    const float* a_src2 = (const float*)d_in[8];
    const float* a_dst2 = (const float*)d_in[9];
    const float* b2     = (const float*)d_in[10];
    float*       out    = (float*)d_out;

    static cudaStream_t s2 = nullptr;
    static cudaEvent_t evFork = nullptr, evJoin = nullptr;
    static void* degPtr = nullptr;
    if (s2 == nullptr) {
        cudaStreamCreateWithFlags(&s2, cudaStreamNonBlocking);
        cudaEventCreateWithFlags(&evFork, cudaEventDisableTiming);
        cudaEventCreateWithFlags(&evJoin, cudaEventDisableTiming);
        cudaGetSymbolAddress(&degPtr, g_deg);
    }

    // fork: CSR build on side stream, overlapped with GEMM1 + alpha1
    cudaEventRecord(evFork, 0);
    cudaStreamWaitEvent(s2, evFork, 0);
    cudaMemsetAsync(degPtr, 0, N_NODES * sizeof(int), s2);
    build_edges_kernel<<<(E_TOT / 4 + 255) / 256, 256, 0, s2>>>(ei);
    scan_kernel<<<1, 1024, 0, s2>>>();
    scatter_kernel<<<(E_TOT / 4 + 255) / 256, 256, 0, s2>>>();
    cudaEventRecord(evJoin, s2);

    gemm1_kernel<<<(N_NODES + 127) / 128, 256>>>(x, W1);
    alpha1_kernel<<<N_NODES, 128>>>(a_src1, a_dst1);

    // join: agg1 needs the CSR
    cudaStreamWaitEvent(0, evJoin, 0);
    agg1_kernel<<<(N_NODES + 7) / 8, 256>>>(b1);

    gemm2_kernel<<<(N_NODES + 127) / 128, 256>>>(W2);
    alpha2_kernel<<<(N_NODES + 7) / 8, 256>>>(a_src2, a_dst2);
    agg2_kernel<<<(N_NODES + 7) / 8, 256>>>(b2, out);
}

// round 9
// speedup vs baseline: 1.3034x; 1.1197x over previous
#include <cuda_runtime.h>
#include <cuda_bf16.h>
#include <cstdint>

#define N_NODES 50000
#define E_ORIG  800000
#define E_TOT   850000   // E_ORIG + N self-loops (both divisible by 4)
#define FULLMASK 0xffffffffu

// ---------------- scratch (static __device__ — no allocation) ----------------
__device__ __align__(16) int   g_src32[E_TOT];
__device__ __align__(16) int   g_dst32[E_TOT];
__device__ __align__(16) int   g_srcs [E_TOT];        // src sorted by dst (CSR)
__device__ __align__(16) int   g_deg[N_NODES];
__device__ __align__(16) int   g_rowstart[N_NODES + 1];
__device__ __align__(16) int   g_cursor[N_NODES];
__device__ __align__(16) float g_h1  [N_NODES * 128]; // x @ W1
__device__ __align__(16) float g_as1 [N_NODES * 4];
__device__ __align__(16) float g_ad1 [N_NODES * 4];
__device__ __align__(16) float g_out1[N_NODES * 128]; // relu(agg1 + b1)
__device__ __align__(16) float g_h2  [N_NODES * 64];  // out1 @ W2
__device__ __align__(16) float g_as2 [N_NODES];
__device__ __align__(16) float g_ad2 [N_NODES];

__device__ __forceinline__ float lrelu(float v) {
    return v > 0.f ? v : 0.2f * v;
}

// packed f32x2 helpers (FFMA2 — ptxas never emits it from C++)
__device__ __forceinline__ unsigned long long pack_dup(float a) {
    unsigned long long r;
    asm("mov.b64 %0, {%1, %1};" : "=l"(r) : "f"(a));
    return r;
}
__device__ __forceinline__ void ffma2(unsigned long long& acc,
                                      unsigned long long a,
                                      unsigned long long b) {
    asm("fma.rn.f32x2 %0, %1, %2, %0;" : "+l"(acc) : "l"(a), "l"(b));
}
__device__ __forceinline__ float2 unpack2(unsigned long long v) {
    float lo, hi;
    asm("mov.b64 {%0, %1}, %2;" : "=f"(lo), "=f"(hi) : "l"(v));
    return make_float2(lo, hi);
}

// ---------------- CSR build ----------------
// edge_index is INT32 (JAX x64 disabled downcasts int64 -> int32)
__global__ void build_edges_kernel(const int* __restrict__ ei) {
    int e = (blockIdx.x * blockDim.x + threadIdx.x) * 4;
    if (e >= E_TOT) return;
    int4 s4, d4;
    if (e < E_ORIG) {                       // E_ORIG % 4 == 0: no straddle
        s4 = *(const int4*)&ei[e];
        d4 = *(const int4*)&ei[E_ORIG + e];
    } else {
        int b = e - E_ORIG;
        s4 = make_int4(b, b + 1, b + 2, b + 3);
        d4 = s4;
    }
    *(int4*)&g_src32[e] = s4;
    *(int4*)&g_dst32[e] = d4;
    if ((unsigned)d4.x < (unsigned)N_NODES) atomicAdd(&g_deg[d4.x], 1);
    if ((unsigned)d4.y < (unsigned)N_NODES) atomicAdd(&g_deg[d4.y], 1);
    if ((unsigned)d4.z < (unsigned)N_NODES) atomicAdd(&g_deg[d4.z], 1);
    if ((unsigned)d4.w < (unsigned)N_NODES) atomicAdd(&g_deg[d4.w], 1);
}

// single-block exclusive scan of g_deg -> g_rowstart, g_cursor
__global__ void scan_kernel() {
    __shared__ int warpoff[32];
    __shared__ int warpsum[32];
    __shared__ int s_carry;
    int tid = threadIdx.x, lane = tid & 31, wid = tid >> 5;
    if (tid == 0) s_carry = 0;
    __syncthreads();
    for (int base = 0; base < N_NODES; base += 1024) {
        int i = base + tid;
        int v = (i < N_NODES) ? g_deg[i] : 0;
        int x = v;
        #pragma unroll
        for (int off = 1; off < 32; off <<= 1) {
            int t = __shfl_up_sync(FULLMASK, x, off);
            if (lane >= off) x += t;
        }
        if (lane == 31) warpsum[wid] = x;
        __syncthreads();
        if (wid == 0) {
            int s = warpsum[lane];
            int y = s;
            #pragma unroll
            for (int off = 1; off < 32; off <<= 1) {
                int t = __shfl_up_sync(FULLMASK, y, off);
                if (lane >= off) y += t;
            }
            warpoff[lane] = y - s;  // exclusive among warps
        }
        __syncthreads();
        int carry = s_carry;
        int excl = carry + warpoff[wid] + (x - v);
        if (i < N_NODES) { g_rowstart[i] = excl; g_cursor[i] = excl; }
        __syncthreads();
        if (tid == 1023) s_carry = carry + warpoff[31] + x;  // chunk total
        __syncthreads();
    }
    if (threadIdx.x == 0) g_rowstart[N_NODES] = s_carry;
}

__global__ void scatter_kernel() {
    int e = (blockIdx.x * blockDim.x + threadIdx.x) * 4;
    if (e >= E_TOT) return;
    int4 d4 = *(const int4*)&g_dst32[e];
    int4 s4 = *(const int4*)&g_src32[e];
    #pragma unroll
    for (int l = 0; l < 4; l++) {
        int d = (l == 0) ? d4.x : (l == 1) ? d4.y : (l == 2) ? d4.z : d4.w;
        int s = (l == 0) ? s4.x : (l == 1) ? s4.y : (l == 2) ? s4.z : s4.w;
        if ((unsigned)d < (unsigned)N_NODES) {
            int pos = atomicAdd(&g_cursor[d], 1);
            if ((unsigned)pos < (unsigned)E_TOT) g_srcs[pos] = s;
        }
    }
}

// ---- GEMM1: h1 = x @ W1 (FFMA2, sw-pipelined) + fused alpha1 epilogue ------
__global__ __launch_bounds__(256, 2) void gemm1_kernel(const float* __restrict__ X,
                                                       const float* __restrict__ W,
                                                       const float* __restrict__ a_src,
                                                       const float* __restrict__ a_dst) {
    __shared__ __align__(16) float As[16][132];
    __shared__ __align__(16) float Bs[16][128];
    int tid = threadIdx.x;
    int tx = tid & 15, ty = tid >> 4;
    int blockRow = blockIdx.x * 128;
    unsigned long long accp[8][4];
    #pragma unroll
    for (int i = 0; i < 8; i++)
        #pragma unroll
        for (int j = 0; j < 4; j++) accp[i][j] = 0ull;

    int id0 = tid * 2, id1 = tid * 2 + 1;
    int xr0 = id0 >> 2, xc0 = (id0 & 3) * 4;
    int xr1 = id1 >> 2, xc1 = (id1 & 3) * 4;
    int wr0 = id0 >> 5, wc0 = (id0 & 31) * 4;
    int wr1 = id1 >> 5, wc1 = (id1 & 31) * 4;
    int grow0 = blockRow + xr0, grow1 = blockRow + xr1;

    float4 xa0 = make_float4(0, 0, 0, 0), xa1 = make_float4(0, 0, 0, 0);
    if (grow0 < N_NODES) xa0 = *(const float4*)&X[grow0 * 128 + xc0];
    if (grow1 < N_NODES) xa1 = *(const float4*)&X[grow1 * 128 + xc1];
    float4 wb0 = *(const float4*)&W[wr0 * 128 + wc0];
    float4 wb1 = *(const float4*)&W[wr1 * 128 + wc1];

    for (int k0 = 0; k0 < 128; k0 += 16) {
        As[xc0 + 0][xr0] = xa0.x; As[xc0 + 1][xr0] = xa0.y;
        As[xc0 + 2][xr0] = xa0.z; As[xc0 + 3][xr0] = xa0.w;
        As[xc1 + 0][xr1] = xa1.x; As[xc1 + 1][xr1] = xa1.y;
        As[xc1 + 2][xr1] = xa1.z; As[xc1 + 3][xr1] = xa1.w;
        *(float4*)&Bs[wr0][wc0] = wb0;
        *(float4*)&Bs[wr1][wc1] = wb1;
        __syncthreads();
        if (k0 + 16 < 128) {   // prefetch next tile while computing this one
            int kn = k0 + 16;
            if (grow0 < N_NODES) xa0 = *(const float4*)&X[grow0 * 128 + kn + xc0];
            if (grow1 < N_NODES) xa1 = *(const float4*)&X[grow1 * 128 + kn + xc1];
            wb0 = *(const float4*)&W[(kn + wr0) * 128 + wc0];
            wb1 = *(const float4*)&W[(kn + wr1) * 128 + wc1];
        }
        #pragma unroll
        for (int k = 0; k < 16; k++) {
            float a[8];
            *(float4*)&a[0] = *(const float4*)&As[k][ty * 4];
            *(float4*)&a[4] = *(const float4*)&As[k][64 + ty * 4];
            unsigned long long bp[4];
            bp[0] = *(const unsigned long long*)&Bs[k][tx * 4];
            bp[1] = *(const unsigned long long*)&Bs[k][tx * 4 + 2];
            bp[2] = *(const unsigned long long*)&Bs[k][64 + tx * 4];
            bp[3] = *(const unsigned long long*)&Bs[k][64 + tx * 4 + 2];
            #pragma unroll
            for (int i = 0; i < 8; i++) {
                unsigned long long ap = pack_dup(a[i]);
                #pragma unroll
                for (int j = 0; j < 4; j++) ffma2(accp[i][j], ap, bp[j]);
            }
        }
        __syncthreads();
    }

    // epilogue: write h1 + fused per-head alpha projections.
    // Thread covers cols [tx*4, tx*4+4) (heads 0/1) and [64+tx*4, ...) (heads 2/3).
    float asl[4], adl[4], ash[4], adh[4];
    #pragma unroll
    for (int j = 0; j < 4; j++) {
        asl[j] = a_src[tx * 4 + j];      adl[j] = a_dst[tx * 4 + j];
        ash[j] = a_src[64 + tx * 4 + j]; adh[j] = a_dst[64 + tx * 4 + j];
    }
    #pragma unroll
    for (int i = 0; i < 8; i++) {
        int gr = blockRow + ((i < 4) ? (ty * 4 + i) : (64 + ty * 4 + i - 4));
        if (gr >= N_NODES) continue;
        float2 p0 = unpack2(accp[i][0]), p1 = unpack2(accp[i][1]);
        float2 p2 = unpack2(accp[i][2]), p3 = unpack2(accp[i][3]);
        *(float4*)&g_h1[gr * 128 + tx * 4]      = make_float4(p0.x, p0.y, p1.x, p1.y);
        *(float4*)&g_h1[gr * 128 + 64 + tx * 4] = make_float4(p2.x, p2.y, p3.x, p3.y);
        float sl = p0.x * asl[0] + p0.y * asl[1] + p1.x * asl[2] + p1.y * asl[3];
        float dl = p0.x * adl[0] + p0.y * adl[1] + p1.x * adl[2] + p1.y * adl[3];
        float sh = p2.x * ash[0] + p2.y * ash[1] + p3.x * ash[2] + p3.y * ash[3];
        float dh = p2.x * adh[0] + p2.y * adh[1] + p3.x * adh[2] + p3.y * adh[3];
        #pragma unroll
        for (int off = 1; off <= 4; off <<= 1) {   // reduce over 8-lane head group
            sl += __shfl_xor_sync(FULLMASK, sl, off);
            dl += __shfl_xor_sync(FULLMASK, dl, off);
            sh += __shfl_xor_sync(FULLMASK, sh, off);
            dh += __shfl_xor_sync(FULLMASK, dh, off);
        }
        if ((tx & 7) == 0) {
            int hl = tx >> 3;           // 0 or 1
            g_as1[gr * 4 + hl] = sl;       g_ad1[gr * 4 + hl] = dl;
            g_as1[gr * 4 + 2 + hl] = sh;   g_ad1[gr * 4 + 2 + hl] = dh;
        }
    }
}

// ---------------- layer-1 aggregation: warp per dst node, online softmax ----
__global__ __launch_bounds__(256) void agg1_kernel(const float* __restrict__ b1) {
    __shared__ float4 sw[8][32];
    __shared__ int    ss[8][32];
    int warpid = threadIdx.x >> 5;
    int lane = threadIdx.x & 31;
    int n = blockIdx.x * 8 + warpid;
    if (n >= N_NODES) return;
    int s0 = g_rowstart[n], s1 = g_rowstart[n + 1];
    float4 ad = *(const float4*)&g_ad1[n * 4];

    // fused max+denom (online softmax)
    float m0 = -1e30f, m1 = -1e30f, m2 = -1e30f, m3 = -1e30f;
    float d0 = 0.f, d1 = 0.f, d2 = 0.f, d3 = 0.f;
    for (int e = s0 + lane; e < s1; e += 32) {
        int s = g_srcs[e];
        float4 a = *(const float4*)&g_as1[s * 4];
        float e0 = lrelu(a.x + ad.x), e1 = lrelu(a.y + ad.y);
        float e2 = lrelu(a.z + ad.z), e3 = lrelu(a.w + ad.w);
        float nm;
        nm = fmaxf(m0, e0); d0 = d0 * __expf(m0 - nm) + __expf(e0 - nm); m0 = nm;
        nm = fmaxf(m1, e1); d1 = d1 * __expf(m1 - nm) + __expf(e1 - nm); m1 = nm;
        nm = fmaxf(m2, e2); d2 = d2 * __expf(m2 - nm) + __expf(e2 - nm); m2 = nm;
        nm = fmaxf(m3, e3); d3 = d3 * __expf(m3 - nm) + __expf(e3 - nm); m3 = nm;
    }
    #pragma unroll
    for (int off = 16; off >= 1; off >>= 1) {
        float om, od, nm;
        om = __shfl_xor_sync(FULLMASK, m0, off); od = __shfl_xor_sync(FULLMASK, d0, off);
        nm = fmaxf(m0, om); d0 = d0 * __expf(m0 - nm) + od * __expf(om - nm); m0 = nm;
        om = __shfl_xor_sync(FULLMASK, m1, off); od = __shfl_xor_sync(FULLMASK, d1, off);
        nm = fmaxf(m1, om); d1 = d1 * __expf(m1 - nm) + od * __expf(om - nm); m1 = nm;
        om = __shfl_xor_sync(FULLMASK, m2, off); od = __shfl_xor_sync(FULLMASK, d2, off);
        nm = fmaxf(m2, om); d2 = d2 * __expf(m2 - nm) + od * __expf(om - nm); m2 = nm;
        om = __shfl_xor_sync(FULLMASK, m3, off); od = __shfl_xor_sync(FULLMASK, d3, off);
        nm = fmaxf(m3, om); d3 = d3 * __expf(m3 - nm) + od * __expf(om - nm); m3 = nm;
    }
    float r0 = 1.f / d0, r1 = 1.f / d1, r2 = 1.f / d2, r3 = 1.f / d3;

    // weighted accumulate; weights staged in smem (LDS broadcast, no shfl storm)
    float acc0 = 0.f, acc1 = 0.f, acc2 = 0.f, acc3 = 0.f;
    for (int base = s0; base < s1; base += 32) {
        int e = base + lane;
        int cnt = min(32, s1 - base);
        if (e < s1) {
            int sl = g_srcs[e];
            float4 a = *(const float4*)&g_as1[sl * 4];
            sw[warpid][lane] = make_float4(__expf(lrelu(a.x + ad.x) - m0) * r0,
                                           __expf(lrelu(a.y + ad.y) - m1) * r1,
                                           __expf(lrelu(a.z + ad.z) - m2) * r2,
                                           __expf(lrelu(a.w + ad.w) - m3) * r3);
            ss[warpid][lane] = sl;
        }
        __syncwarp();
        for (int j = 0; j < cnt; j++) {
            float4 wj = sw[warpid][j];
            int s = ss[warpid][j];
            const float* hp = g_h1 + s * 128 + lane;
            acc0 = fmaf(hp[0],  wj.x, acc0);
            acc1 = fmaf(hp[32], wj.y, acc1);
            acc2 = fmaf(hp[64], wj.z, acc2);
            acc3 = fmaf(hp[96], wj.w, acc3);
        }
        __syncwarp();
    }
    int o = n * 128 + lane;
    g_out1[o]      = fmaxf(acc0 + b1[lane],      0.f);
    g_out1[o + 32] = fmaxf(acc1 + b1[lane + 32], 0.f);
    g_out1[o + 64] = fmaxf(acc2 + b1[lane + 64], 0.f);
    g_out1[o + 96] = fmaxf(acc3 + b1[lane + 96], 0.f);
}

// ---- GEMM2: h2 = out1 @ W2 (FFMA2, sw-pipelined) + fused alpha2 epilogue ---
__global__ __launch_bounds__(256, 2) void gemm2_kernel(const float* __restrict__ W,
                                                       const float* __restrict__ a_src,
                                                       const float* __restrict__ a_dst) {
    __shared__ __align__(16) float As[16][132];
    __shared__ __align__(16) float Bs[16][64];
    int tid = threadIdx.x;
    int tx = tid & 15, ty = tid >> 4;
    int blockRow = blockIdx.x * 128;
    unsigned long long accp[8][2];
    #pragma unroll
    for (int i = 0; i < 8; i++) { accp[i][0] = 0ull; accp[i][1] = 0ull; }

    int id0 = tid * 2, id1 = tid * 2 + 1;
    int xr0 = id0 >> 2, xc0 = (id0 & 3) * 4;
    int xr1 = id1 >> 2, xc1 = (id1 & 3) * 4;
    int wr = tid >> 4, wc = (tid & 15) * 4;
    int grow0 = blockRow + xr0, grow1 = blockRow + xr1;

    float4 xa0 = make_float4(0, 0, 0, 0), xa1 = make_float4(0, 0, 0, 0);
    if (grow0 < N_NODES) xa0 = *(const float4*)&g_out1[grow0 * 128 + xc0];
    if (grow1 < N_NODES) xa1 = *(const float4*)&g_out1[grow1 * 128 + xc1];
    float4 wb = *(const float4*)&W[wr * 64 + wc];

    for (int k0 = 0; k0 < 128; k0 += 16) {
        As[xc0 + 0][xr0] = xa0.x; As[xc0 + 1][xr0] = xa0.y;
        As[xc0 + 2][xr0] = xa0.z; As[xc0 + 3][xr0] = xa0.w;
        As[xc1 + 0][xr1] = xa1.x; As[xc1 + 1][xr1] = xa1.y;
        As[xc1 + 2][xr1] = xa1.z; As[xc1 + 3][xr1] = xa1.w;
        *(float4*)&Bs[wr][wc] = wb;
        __syncthreads();
        if (k0 + 16 < 128) {
            int kn = k0 + 16;
            if (grow0 < N_NODES) xa0 = *(const float4*)&g_out1[grow0 * 128 + kn + xc0];
            if (grow1 < N_NODES) xa1 = *(const float4*)&g_out1[grow1 * 128 + kn + xc1];
            wb = *(const float4*)&W[(kn + wr) * 64 + wc];
        }
        #pragma unroll
        for (int k = 0; k < 16; k++) {
            float a[8];
            *(float4*)&a[0] = *(const float4*)&As[k][ty * 4];
            *(float4*)&a[4] = *(const float4*)&As[k][64 + ty * 4];
            unsigned long long bp[2];
            bp[0] = *(const unsigned long long*)&Bs[k][tx * 4];
            bp[1] = *(const unsigned long long*)&Bs[k][tx * 4 + 2];
            #pragma unroll
            for (int i = 0; i < 8; i++) {
                unsigned long long ap = pack_dup(a[i]);
                ffma2(accp[i][0], ap, bp[0]);
                ffma2(accp[i][1], ap, bp[1]);
            }
        }
        __syncthreads();
    }

    // epilogue: write h2 + fused alpha2 (single head over 64 cols)
    float as4[4], ad4[4];
    #pragma unroll
    for (int j = 0; j < 4; j++) {
        as4[j] = a_src[tx * 4 + j];
        ad4[j] = a_dst[tx * 4 + j];
    }
    #pragma unroll
    for (int i = 0; i < 8; i++) {
        int gr = blockRow + ((i < 4) ? (ty * 4 + i) : (64 + ty * 4 + i - 4));
        if (gr >= N_NODES) continue;
        float2 p0 = unpack2(accp[i][0]), p1 = unpack2(accp[i][1]);
        *(float4*)&g_h2[gr * 64 + tx * 4] = make_float4(p0.x, p0.y, p1.x, p1.y);
        float ps = p0.x * as4[0] + p0.y * as4[1] + p1.x * as4[2] + p1.y * as4[3];
        float pd = p0.x * ad4[0] + p0.y * ad4[1] + p1.x * ad4[2] + p1.y * ad4[3];
        #pragma unroll
        for (int off = 1; off <= 8; off <<= 1) {   // reduce over 16-lane half-warp
            ps += __shfl_xor_sync(FULLMASK, ps, off);
            pd += __shfl_xor_sync(FULLMASK, pd, off);
        }
        if (tx == 0) { g_as2[gr] = ps; g_ad2[gr] = pd; }
    }
}

// ---------------- layer-2 aggregation: warp per dst node -> d_out ----------
__global__ __launch_bounds__(256) void agg2_kernel(const float* __restrict__ b2,
                                                   float* __restrict__ out) {
    __shared__ float sw[8][32];
    __shared__ int   ss[8][32];
    int warpid = threadIdx.x >> 5;
    int lane = threadIdx.x & 31;
    int n = blockIdx.x * 8 + warpid;
    if (n >= N_NODES) return;
    int s0 = g_rowstart[n], s1 = g_rowstart[n + 1];
    float ad = g_ad2[n];

    float m = -1e30f, d = 0.f;
    for (int e = s0 + lane; e < s1; e += 32) {
        float ev = lrelu(g_as2[g_srcs[e]] + ad);
        float nm = fmaxf(m, ev);
        d = d * __expf(m - nm) + __expf(ev - nm);
        m = nm;
    }
    #pragma unroll
    for (int off = 16; off >= 1; off >>= 1) {
        float om = __shfl_xor_sync(FULLMASK, m, off);
        float od = __shfl_xor_sync(FULLMASK, d, off);
        float nm = fmaxf(m, om);
        d = d * __expf(m - nm) + od * __expf(om - nm);
        m = nm;
    }
    float rd = 1.f / d;

    float acc0 = 0.f, acc1 = 0.f;
    for (int base = s0; base < s1; base += 32) {
        int e = base + lane;
        int cnt = min(32, s1 - base);
        if (e < s1) {
            int sl = g_srcs[e];
            sw[warpid][lane] = __expf(lrelu(g_as2[sl] + ad) - m) * rd;
            ss[warpid][lane] = sl;
        }
        __syncwarp();
        for (int j = 0; j < cnt; j++) {
            float wj = sw[warpid][j];
            int s = ss[warpid][j];
            const float* hp = g_h2 + s * 64 + lane;
            acc0 = fmaf(hp[0],  wj, acc0);
            acc1 = fmaf(hp[32], wj, acc1);
        }
        __syncwarp();
    }
    out[n * 64 + lane]      = acc0 + b2[lane];
    out[n * 64 + 32 + lane] = acc1 + b2[32 + lane];
}

// ---------------- launcher ----------------
extern "C" void kernel_launch(void* const* d_in, const int* in_sizes, int n_in,
                              void* d_out, int out_size) {
    const float* x      = (const float*)d_in[0];
    const int*   ei     = (const int*)d_in[1];   // int32 (JAX x64 disabled)
    // d_in[2] edge_weight unused (PyG GATConv ignores it with edge_dim unset)
    const float* W1     = (const float*)d_in[3];
    const float* a_src1 = (const float*)d_in[4];
    const float* a_dst1 = (const float*)d_in[5];
    const float* b1     = (const float*)d_in[6];
    const float* W2     = (const float*)d_in[7];
    const float* a_src2 = (const float*)d_in[8];
    const float* a_dst2 = (const float*)d_in[9];
    const float* b2     = (const float*)d_in[10];
    float*       out    = (float*)d_out;

    static cudaStream_t s2 = nullptr;
    static cudaEvent_t evFork = nullptr, evJoin = nullptr;
    static void* degPtr = nullptr;
    if (s2 == nullptr) {
        cudaStreamCreateWithFlags(&s2, cudaStreamNonBlocking);
        cudaEventCreateWithFlags(&evFork, cudaEventDisableTiming);
        cudaEventCreateWithFlags(&evJoin, cudaEventDisableTiming);
        cudaGetSymbolAddress(&degPtr, g_deg);
    }

    // fork: CSR build on side stream, overlapped with GEMM1
    cudaEventRecord(evFork, 0);
    cudaStreamWaitEvent(s2, evFork, 0);
    cudaMemsetAsync(degPtr, 0, N_NODES * sizeof(int), s2);
    build_edges_kernel<<<(E_TOT / 4 + 255) / 256, 256, 0, s2>>>(ei);
    scan_kernel<<<1, 1024, 0, s2>>>();
    scatter_kernel<<<(E_TOT / 4 + 255) / 256, 256, 0, s2>>>();
    cudaEventRecord(evJoin, s2);

    gemm1_kernel<<<(N_NODES + 127) / 128, 256>>>(x, W1, a_src1, a_dst1);

    // join: agg1 needs the CSR
    cudaStreamWaitEvent(0, evJoin, 0);
    agg1_kernel<<<(N_NODES + 7) / 8, 256>>>(b1);

    gemm2_kernel<<<(N_NODES + 127) / 128, 256>>>(W2, a_src2, a_dst2);
    agg2_kernel<<<(N_NODES + 7) / 8, 256>>>(b2, out);
}

// round 12
// speedup vs baseline: 1.4287x; 1.0962x over previous
#include <cuda_runtime.h>
#include <cuda_bf16.h>
#include <cstdint>

#define N_NODES 50000
#define E_ORIG  800000
#define E_TOT   850000   // E_ORIG + N self-loops (both divisible by 4)
#define NBLK    196      // ceil(N_NODES/256)
#define FULLMASK 0xffffffffu

// ---------------- scratch (static __device__ — no allocation) ----------------
__device__ __align__(16) int   g_srcs [E_TOT];        // src sorted by dst (CSR)
__device__ __align__(16) int   g_deg[N_NODES];
__device__ __align__(16) int   g_rowstart[N_NODES + 1];
__device__ __align__(16) int   g_cursor[N_NODES];
__device__ __align__(16) int   g_blocksum[NBLK];
__device__ __align__(16) int   g_blockoff[NBLK];
__device__ __align__(16) float g_h1  [N_NODES * 128]; // x @ W1
__device__ __align__(16) float g_as1 [N_NODES * 4];
__device__ __align__(16) float g_ad1 [N_NODES * 4];
__device__ __align__(16) float g_out1[N_NODES * 128]; // relu(agg1 + b1)
__device__ __align__(16) float g_h2  [N_NODES * 64];  // out1 @ W2
__device__ __align__(16) float g_as2 [N_NODES];
__device__ __align__(16) float g_ad2 [N_NODES];

__device__ __forceinline__ float lrelu(float v) {
    return v > 0.f ? v : 0.2f * v;
}

// packed f32x2 helpers (FFMA2 — ptxas never emits it from C++)
__device__ __forceinline__ unsigned long long pack_dup(float a) {
    unsigned long long r;
    asm("mov.b64 %0, {%1, %1};" : "=l"(r) : "f"(a));
    return r;
}
__device__ __forceinline__ void ffma2(unsigned long long& acc,
                                      unsigned long long a,
                                      unsigned long long b) {
    asm("fma.rn.f32x2 %0, %1, %2, %0;" : "+l"(acc) : "l"(a), "l"(b));
}
__device__ __forceinline__ float2 unpack2(unsigned long long v) {
    float lo, hi;
    asm("mov.b64 {%0, %1}, %2;" : "=f"(lo), "=f"(hi) : "l"(v));
    return make_float2(lo, hi);
}

// ---------------- CSR build ----------------
// edge_index is INT32 (JAX x64 disabled downcasts int64 -> int32)
__global__ void build_deg_kernel(const int* __restrict__ ei) {
    int e = (blockIdx.x * blockDim.x + threadIdx.x) * 4;
    if (e >= E_TOT) return;
    int4 d4;
    if (e < E_ORIG) {
        d4 = *(const int4*)&ei[E_ORIG + e];
    } else {
        int b = e - E_ORIG;
        d4 = make_int4(b, b + 1, b + 2, b + 3);
    }
    if ((unsigned)d4.x < (unsigned)N_NODES) atomicAdd(&g_deg[d4.x], 1);
    if ((unsigned)d4.y < (unsigned)N_NODES) atomicAdd(&g_deg[d4.y], 1);
    if ((unsigned)d4.z < (unsigned)N_NODES) atomicAdd(&g_deg[d4.z], 1);
    if ((unsigned)d4.w < (unsigned)N_NODES) atomicAdd(&g_deg[d4.w], 1);
}

// parallel scan stage 1: per-block exclusive scan (partial) + block sums
__global__ void scan1_kernel() {
    __shared__ int wsum[8], woff[8];
    int tid = threadIdx.x, lane = tid & 31, wid = tid >> 5;
    int i = blockIdx.x * 256 + tid;
    int v = (i < N_NODES) ? g_deg[i] : 0;
    int x = v;
    #pragma unroll
    for (int off = 1; off < 32; off <<= 1) {
        int t = __shfl_up_sync(FULLMASK, x, off);
        if (lane >= off) x += t;
    }
    if (lane == 31) wsum[wid] = x;
    __syncthreads();
    if (wid == 0 && lane < 8) {
        int s = wsum[lane];
        int y = s;
        #pragma unroll
        for (int off = 1; off < 8; off <<= 1) {
            int t = __shfl_up_sync(0xffu, y, off);
            if (lane >= off) y += t;
        }
        woff[lane] = y - s;
        if (lane == 7) g_blocksum[blockIdx.x] = y;
    }
    __syncthreads();
    if (i < N_NODES) g_rowstart[i] = woff[wid] + (x - v);   // partial (in-block)
}

// stage 2: single-block exclusive scan of NBLK block sums
__global__ void scan2_kernel() {
    __shared__ int wsum[8], woff[8];
    int tid = threadIdx.x, lane = tid & 31, wid = tid >> 5;
    int v = (tid < NBLK) ? g_blocksum[tid] : 0;
    int x = v;
    #pragma unroll
    for (int off = 1; off < 32; off <<= 1) {
        int t = __shfl_up_sync(FULLMASK, x, off);
        if (lane >= off) x += t;
    }
    if (lane == 31) wsum[wid] = x;
    __syncthreads();
    if (wid == 0 && lane < 8) {
        int s = wsum[lane];
        int y = s;
        #pragma unroll
        for (int off = 1; off < 8; off <<= 1) {
            int t = __shfl_up_sync(0xffu, y, off);
            if (lane >= off) y += t;
        }
        woff[lane] = y - s;
        if (lane == 7) g_rowstart[N_NODES] = y;   // total = E_TOT
    }
    __syncthreads();
    if (tid < NBLK) g_blockoff[tid] = woff[wid] + (x - v);
}

// stage 3: add block offsets -> final rowstart + cursor
__global__ void scan3_kernel() {
    int i = blockIdx.x * 256 + threadIdx.x;
    if (i < N_NODES) {
        int r = g_rowstart[i] + g_blockoff[blockIdx.x];
        g_rowstart[i] = r;
        g_cursor[i] = r;
    }
}

__global__ void scatter_kernel(const int* __restrict__ ei) {
    int e = (blockIdx.x * blockDim.x + threadIdx.x) * 4;
    if (e >= E_TOT) return;
    int4 s4, d4;
    if (e < E_ORIG) {
        s4 = *(const int4*)&ei[e];
        d4 = *(const int4*)&ei[E_ORIG + e];
    } else {
        int b = e - E_ORIG;
        s4 = make_int4(b, b + 1, b + 2, b + 3);
        d4 = s4;
    }
    #pragma unroll
    for (int l = 0; l < 4; l++) {
        int d = (l == 0) ? d4.x : (l == 1) ? d4.y : (l == 2) ? d4.z : d4.w;
        int s = (l == 0) ? s4.x : (l == 1) ? s4.y : (l == 2) ? s4.z : s4.w;
        if ((unsigned)d < (unsigned)N_NODES) {
            int pos = atomicAdd(&g_cursor[d], 1);
            if ((unsigned)pos < (unsigned)E_TOT) g_srcs[pos] = s;
        }
    }
}

// ---- GEMM1: h1 = x @ W1 (FFMA2, sw-pipelined) + fused alpha1 epilogue ------
__global__ __launch_bounds__(256, 2) void gemm1_kernel(const float* __restrict__ X,
                                                       const float* __restrict__ W,
                                                       const float* __restrict__ a_src,
                                                       const float* __restrict__ a_dst) {
    __shared__ __align__(16) float As[16][132];
    __shared__ __align__(16) float Bs[16][128];
    int tid = threadIdx.x;
    int tx = tid & 15, ty = tid >> 4;
    int blockRow = blockIdx.x * 128;
    unsigned long long accp[8][4];
    #pragma unroll
    for (int i = 0; i < 8; i++)
        #pragma unroll
        for (int j = 0; j < 4; j++) accp[i][j] = 0ull;

    int id0 = tid * 2, id1 = tid * 2 + 1;
    int xr0 = id0 >> 2, xc0 = (id0 & 3) * 4;
    int xr1 = id1 >> 2, xc1 = (id1 & 3) * 4;
    int wr0 = id0 >> 5, wc0 = (id0 & 31) * 4;
    int wr1 = id1 >> 5, wc1 = (id1 & 31) * 4;
    int grow0 = blockRow + xr0, grow1 = blockRow + xr1;

    float4 xa0 = make_float4(0, 0, 0, 0), xa1 = make_float4(0, 0, 0, 0);
    if (grow0 < N_NODES) xa0 = *(const float4*)&X[grow0 * 128 + xc0];
    if (grow1 < N_NODES) xa1 = *(const float4*)&X[grow1 * 128 + xc1];
    float4 wb0 = *(const float4*)&W[wr0 * 128 + wc0];
    float4 wb1 = *(const float4*)&W[wr1 * 128 + wc1];

    for (int k0 = 0; k0 < 128; k0 += 16) {
        As[xc0 + 0][xr0] = xa0.x; As[xc0 + 1][xr0] = xa0.y;
        As[xc0 + 2][xr0] = xa0.z; As[xc0 + 3][xr0] = xa0.w;
        As[xc1 + 0][xr1] = xa1.x; As[xc1 + 1][xr1] = xa1.y;
        As[xc1 + 2][xr1] = xa1.z; As[xc1 + 3][xr1] = xa1.w;
        *(float4*)&Bs[wr0][wc0] = wb0;
        *(float4*)&Bs[wr1][wc1] = wb1;
        __syncthreads();
        if (k0 + 16 < 128) {   // prefetch next tile while computing this one
            int kn = k0 + 16;
            if (grow0 < N_NODES) xa0 = *(const float4*)&X[grow0 * 128 + kn + xc0];
            if (grow1 < N_NODES) xa1 = *(const float4*)&X[grow1 * 128 + kn + xc1];
            wb0 = *(const float4*)&W[(kn + wr0) * 128 + wc0];
            wb1 = *(const float4*)&W[(kn + wr1) * 128 + wc1];
        }
        #pragma unroll
        for (int k = 0; k < 16; k++) {
            float a[8];
            *(float4*)&a[0] = *(const float4*)&As[k][ty * 4];
            *(float4*)&a[4] = *(const float4*)&As[k][64 + ty * 4];
            unsigned long long bp[4];
            bp[0] = *(const unsigned long long*)&Bs[k][tx * 4];
            bp[1] = *(const unsigned long long*)&Bs[k][tx * 4 + 2];
            bp[2] = *(const unsigned long long*)&Bs[k][64 + tx * 4];
            bp[3] = *(const unsigned long long*)&Bs[k][64 + tx * 4 + 2];
            #pragma unroll
            for (int i = 0; i < 8; i++) {
                unsigned long long ap = pack_dup(a[i]);
                #pragma unroll
                for (int j = 0; j < 4; j++) ffma2(accp[i][j], ap, bp[j]);
            }
        }
        __syncthreads();
    }

    float asl[4], adl[4], ash[4], adh[4];
    #pragma unroll
    for (int j = 0; j < 4; j++) {
        asl[j] = a_src[tx * 4 + j];      adl[j] = a_dst[tx * 4 + j];
        ash[j] = a_src[64 + tx * 4 + j]; adh[j] = a_dst[64 + tx * 4 + j];
    }
    #pragma unroll
    for (int i = 0; i < 8; i++) {
        int gr = blockRow + ((i < 4) ? (ty * 4 + i) : (64 + ty * 4 + i - 4));
        if (gr >= N_NODES) continue;
        float2 p0 = unpack2(accp[i][0]), p1 = unpack2(accp[i][1]);
        float2 p2 = unpack2(accp[i][2]), p3 = unpack2(accp[i][3]);
        *(float4*)&g_h1[gr * 128 + tx * 4]      = make_float4(p0.x, p0.y, p1.x, p1.y);
        *(float4*)&g_h1[gr * 128 + 64 + tx * 4] = make_float4(p2.x, p2.y, p3.x, p3.y);
        float sl = p0.x * asl[0] + p0.y * asl[1] + p1.x * asl[2] + p1.y * asl[3];
        float dl = p0.x * adl[0] + p0.y * adl[1] + p1.x * adl[2] + p1.y * adl[3];
        float sh = p2.x * ash[0] + p2.y * ash[1] + p3.x * ash[2] + p3.y * ash[3];
        float dh = p2.x * adh[0] + p2.y * adh[1] + p3.x * adh[2] + p3.y * adh[3];
        #pragma unroll
        for (int off = 1; off <= 4; off <<= 1) {
            sl += __shfl_xor_sync(FULLMASK, sl, off);
            dl += __shfl_xor_sync(FULLMASK, dl, off);
            sh += __shfl_xor_sync(FULLMASK, sh, off);
            dh += __shfl_xor_sync(FULLMASK, dh, off);
        }
        if ((tx & 7) == 0) {
            int hl = tx >> 3;
            g_as1[gr * 4 + hl] = sl;       g_ad1[gr * 4 + hl] = dl;
            g_as1[gr * 4 + 2 + hl] = sh;   g_ad1[gr * 4 + 2 + hl] = dh;
        }
    }
}

// ---------------- layer-1 aggregation: warp per dst node, online softmax ----
__global__ __launch_bounds__(256) void agg1_kernel(const float* __restrict__ b1) {
    __shared__ float4 sw[8][2][32];
    __shared__ int    ss[8][2][32];
    int warpid = threadIdx.x >> 5;
    int lane = threadIdx.x & 31;
    int n = blockIdx.x * 8 + warpid;
    if (n >= N_NODES) return;
    int s0 = g_rowstart[n], s1 = g_rowstart[n + 1];
    float4 ad = *(const float4*)&g_ad1[n * 4];

    float m0 = -1e30f, m1 = -1e30f, m2 = -1e30f, m3 = -1e30f;
    float d0 = 0.f, d1 = 0.f, d2 = 0.f, d3 = 0.f;
    for (int e = s0 + lane; e < s1; e += 32) {
        int s = g_srcs[e];
        float4 a = *(const float4*)&g_as1[s * 4];
        float e0 = lrelu(a.x + ad.x), e1 = lrelu(a.y + ad.y);
        float e2 = lrelu(a.z + ad.z), e3 = lrelu(a.w + ad.w);
        float nm;
        nm = fmaxf(m0, e0); d0 = d0 * __expf(m0 - nm) + __expf(e0 - nm); m0 = nm;
        nm = fmaxf(m1, e1); d1 = d1 * __expf(m1 - nm) + __expf(e1 - nm); m1 = nm;
        nm = fmaxf(m2, e2); d2 = d2 * __expf(m2 - nm) + __expf(e2 - nm); m2 = nm;
        nm = fmaxf(m3, e3); d3 = d3 * __expf(m3 - nm) + __expf(e3 - nm); m3 = nm;
    }
    #pragma unroll
    for (int off = 16; off >= 1; off >>= 1) {
        float om, od, nm;
        om = __shfl_xor_sync(FULLMASK, m0, off); od = __shfl_xor_sync(FULLMASK, d0, off);
        nm = fmaxf(m0, om); d0 = d0 * __expf(m0 - nm) + od * __expf(om - nm); m0 = nm;
        om = __shfl_xor_sync(FULLMASK, m1, off); od = __shfl_xor_sync(FULLMASK, d1, off);
        nm = fmaxf(m1, om); d1 = d1 * __expf(m1 - nm) + od * __expf(om - nm); m1 = nm;
        om = __shfl_xor_sync(FULLMASK, m2, off); od = __shfl_xor_sync(FULLMASK, d2, off);
        nm = fmaxf(m2, om); d2 = d2 * __expf(m2 - nm) + od * __expf(om - nm); m2 = nm;
        om = __shfl_xor_sync(FULLMASK, m3, off); od = __shfl_xor_sync(FULLMASK, d3, off);
        nm = fmaxf(m3, om); d3 = d3 * __expf(m3 - nm) + od * __expf(om - nm); m3 = nm;
    }
    float r0 = 1.f / d0, r1 = 1.f / d1, r2 = 1.f / d2, r3 = 1.f / d3;

    float acc0 = 0.f, acc1 = 0.f, acc2 = 0.f, acc3 = 0.f;
    int buf = 0;
    {
        int e = s0 + lane;
        if (e < s1) {
            int sl = g_srcs[e];
            float4 a = *(const float4*)&g_as1[sl * 4];
            sw[warpid][0][lane] = make_float4(__expf(lrelu(a.x + ad.x) - m0) * r0,
                                              __expf(lrelu(a.y + ad.y) - m1) * r1,
                                              __expf(lrelu(a.z + ad.z) - m2) * r2,
                                              __expf(lrelu(a.w + ad.w) - m3) * r3);
            ss[warpid][0][lane] = sl;
        }
    }
    __syncwarp();
    for (int base = s0; base < s1; base += 32) {
        int nb = base + 32;
        if (nb < s1) {
            int e = nb + lane;
            if (e < s1) {
                int sl = g_srcs[e];
                float4 a = *(const float4*)&g_as1[sl * 4];
                sw[warpid][buf ^ 1][lane] =
                    make_float4(__expf(lrelu(a.x + ad.x) - m0) * r0,
                                __expf(lrelu(a.y + ad.y) - m1) * r1,
                                __expf(lrelu(a.z + ad.z) - m2) * r2,
                                __expf(lrelu(a.w + ad.w) - m3) * r3);
                ss[warpid][buf ^ 1][lane] = sl;
            }
        }
        int cnt = min(32, s1 - base);
        #pragma unroll 4
        for (int j = 0; j < cnt; j++) {
            float4 wj = sw[warpid][buf][j];
            int s = ss[warpid][buf][j];
            const float* hp = g_h1 + s * 128 + lane;
            acc0 = fmaf(hp[0],  wj.x, acc0);
            acc1 = fmaf(hp[32], wj.y, acc1);
            acc2 = fmaf(hp[64], wj.z, acc2);
            acc3 = fmaf(hp[96], wj.w, acc3);
        }
        __syncwarp();
        buf ^= 1;
    }
    int o = n * 128 + lane;
    g_out1[o]      = fmaxf(acc0 + b1[lane],      0.f);
    g_out1[o + 32] = fmaxf(acc1 + b1[lane + 32], 0.f);
    g_out1[o + 64] = fmaxf(acc2 + b1[lane + 64], 0.f);
    g_out1[o + 96] = fmaxf(acc3 + b1[lane + 96], 0.f);
}

// ---- GEMM2: h2 = out1 @ W2 (FFMA2, sw-pipelined) + fused alpha2 epilogue ---
__global__ __launch_bounds__(256, 2) void gemm2_kernel(const float* __restrict__ W,
                                                       const float* __restrict__ a_src,
                                                       const float* __restrict__ a_dst) {
    __shared__ __align__(16) float As[16][132];
    __shared__ __align__(16) float Bs[16][64];
    int tid = threadIdx.x;
    int tx = tid & 15, ty = tid >> 4;
    int blockRow = blockIdx.x * 128;
    unsigned long long accp[8][2];
    #pragma unroll
    for (int i = 0; i < 8; i++) { accp[i][0] = 0ull; accp[i][1] = 0ull; }

    int id0 = tid * 2, id1 = tid * 2 + 1;
    int xr0 = id0 >> 2, xc0 = (id0 & 3) * 4;
    int xr1 = id1 >> 2, xc1 = (id1 & 3) * 4;
    int wr = tid >> 4, wc = (tid & 15) * 4;
    int grow0 = blockRow + xr0, grow1 = blockRow + xr1;

    float4 xa0 = make_float4(0, 0, 0, 0), xa1 = make_float4(0, 0, 0, 0);
    if (grow0 < N_NODES) xa0 = *(const float4*)&g_out1[grow0 * 128 + xc0];
    if (grow1 < N_NODES) xa1 = *(const float4*)&g_out1[grow1 * 128 + xc1];
    float4 wb = *(const float4*)&W[wr * 64 + wc];

    for (int k0 = 0; k0 < 128; k0 += 16) {
        As[xc0 + 0][xr0] = xa0.x; As[xc0 + 1][xr0] = xa0.y;
        As[xc0 + 2][xr0] = xa0.z; As[xc0 + 3][xr0] = xa0.w;
        As[xc1 + 0][xr1] = xa1.x; As[xc1 + 1][xr1] = xa1.y;
        As[xc1 + 2][xr1] = xa1.z; As[xc1 + 3][xr1] = xa1.w;
        *(float4*)&Bs[wr][wc] = wb;
        __syncthreads();
        if (k0 + 16 < 128) {
            int kn = k0 + 16;
            if (grow0 < N_NODES) xa0 = *(const float4*)&g_out1[grow0 * 128 + kn + xc0];
            if (grow1 < N_NODES) xa1 = *(const float4*)&g_out1[grow1 * 128 + kn + xc1];
            wb = *(const float4*)&W[(kn + wr) * 64 + wc];
        }
        #pragma unroll
        for (int k = 0; k < 16; k++) {
            float a[8];
            *(float4*)&a[0] = *(const float4*)&As[k][ty * 4];
            *(float4*)&a[4] = *(const float4*)&As[k][64 + ty * 4];
            unsigned long long bp[2];
            bp[0] = *(const unsigned long long*)&Bs[k][tx * 4];
            bp[1] = *(const unsigned long long*)&Bs[k][tx * 4 + 2];
            #pragma unroll
            for (int i = 0; i < 8; i++) {
                unsigned long long ap = pack_dup(a[i]);
                ffma2(accp[i][0], ap, bp[0]);
                ffma2(accp[i][1], ap, bp[1]);
            }
        }
        __syncthreads();
    }

    float as4[4], ad4[4];
    #pragma unroll
    for (int j = 0; j < 4; j++) {
        as4[j] = a_src[tx * 4 + j];
        ad4[j] = a_dst[tx * 4 + j];
    }
    #pragma unroll
    for (int i = 0; i < 8; i++) {
        int gr = blockRow + ((i < 4) ? (ty * 4 + i) : (64 + ty * 4 + i - 4));
        if (gr >= N_NODES) continue;
        float2 p0 = unpack2(accp[i][0]), p1 = unpack2(accp[i][1]);
        *(float4*)&g_h2[gr * 64 + tx * 4] = make_float4(p0.x, p0.y, p1.x, p1.y);
        float ps = p0.x * as4[0] + p0.y * as4[1] + p1.x * as4[2] + p1.y * as4[3];
        float pd = p0.x * ad4[0] + p0.y * ad4[1] + p1.x * ad4[2] + p1.y * ad4[3];
        #pragma unroll
        for (int off = 1; off <= 8; off <<= 1) {
            ps += __shfl_xor_sync(FULLMASK, ps, off);
            pd += __shfl_xor_sync(FULLMASK, pd, off);
        }
        if (tx == 0) { g_as2[gr] = ps; g_ad2[gr] = pd; }
    }
}

// ---------------- layer-2 aggregation: warp per dst node -> d_out ----------
__global__ __launch_bounds__(256) void agg2_kernel(const float* __restrict__ b2,
                                                   float* __restrict__ out) {
    __shared__ float sw[8][2][32];
    __shared__ int   ss[8][2][32];
    int warpid = threadIdx.x >> 5;
    int lane = threadIdx.x & 31;
    int n = blockIdx.x * 8 + warpid;
    if (n >= N_NODES) return;
    int s0 = g_rowstart[n], s1 = g_rowstart[n + 1];
    float ad = g_ad2[n];

    float m = -1e30f, d = 0.f;
    for (int e = s0 + lane; e < s1; e += 32) {
        float ev = lrelu(g_as2[g_srcs[e]] + ad);
        float nm = fmaxf(m, ev);
        d = d * __expf(m - nm) + __expf(ev - nm);
        m = nm;
    }
    #pragma unroll
    for (int off = 16; off >= 1; off >>= 1) {
        float om = __shfl_xor_sync(FULLMASK, m, off);
        float od = __shfl_xor_sync(FULLMASK, d, off);
        float nm = fmaxf(m, om);
        d = d * __expf(m - nm) + od * __expf(om - nm);
        m = nm;
    }
    float rd = 1.f / d;

    float acc0 = 0.f, acc1 = 0.f;
    int buf = 0;
    {
        int e = s0 + lane;
        if (e < s1) {
            int sl = g_srcs[e];
            sw[warpid][0][lane] = __expf(lrelu(g_as2[sl] + ad) - m) * rd;
            ss[warpid][0][lane] = sl;
        }
    }
    __syncwarp();
    for (int base = s0; base < s1; base += 32) {
        int nb = base + 32;
        if (nb < s1) {
            int e = nb + lane;
            if (e < s1) {
                int sl = g_srcs[e];
                sw[warpid][buf ^ 1][lane] = __expf(lrelu(g_as2[sl] + ad) - m) * rd;
                ss[warpid][buf ^ 1][lane] = sl;
            }
        }
        int cnt = min(32, s1 - base);
        #pragma unroll 4
        for (int j = 0; j < cnt; j++) {
            float wj = sw[warpid][buf][j];
            int s = ss[warpid][buf][j];
            const float* hp = g_h2 + s * 64 + lane;
            acc0 = fmaf(hp[0],  wj, acc0);
            acc1 = fmaf(hp[32], wj, acc1);
        }
        __syncwarp();
        buf ^= 1;
    }
    out[n * 64 + lane]      = acc0 + b2[lane];
    out[n * 64 + 32 + lane] = acc1 + b2[32 + lane];
}

// ---------------- launcher ----------------
extern "C" void kernel_launch(void* const* d_in, const int* in_sizes, int n_in,
                              void* d_out, int out_size) {
    const float* x      = (const float*)d_in[0];
    const int*   ei     = (const int*)d_in[1];   // int32 (JAX x64 disabled)
    // d_in[2] edge_weight unused (PyG GATConv ignores it with edge_dim unset)
    const float* W1     = (const float*)d_in[3];
    const float* a_src1 = (const float*)d_in[4];
    const float* a_dst1 = (const float*)d_in[5];
    const float* b1     = (const float*)d_in[6];
    const float* W2     = (const float*)d_in[7];
    const float* a_src2 = (const float*)d_in[8];
    const float* a_dst2 = (const float*)d_in[9];
    const float* b2     = (const float*)d_in[10];
    float*       out    = (float*)d_out;

    static cudaStream_t s2 = nullptr;
    static cudaEvent_t evFork = nullptr, evJoin = nullptr;
    static void* degPtr = nullptr;
    if (s2 == nullptr) {
        cudaStreamCreateWithFlags(&s2, cudaStreamNonBlocking);
        cudaEventCreateWithFlags(&evFork, cudaEventDisableTiming);
        cudaEventCreateWithFlags(&evJoin, cudaEventDisableTiming);
        cudaGetSymbolAddress(&degPtr, g_deg);
    }

    // fork: CSR build on side stream, overlapped with GEMM1
    cudaEventRecord(evFork, 0);
    cudaStreamWaitEvent(s2, evFork, 0);
    cudaMemsetAsync(degPtr, 0, N_NODES * sizeof(int), s2);
    build_deg_kernel<<<(E_TOT / 4 + 255) / 256, 256, 0, s2>>>(ei);
    scan1_kernel<<<NBLK, 256, 0, s2>>>();
    scan2_kernel<<<1, 256, 0, s2>>>();
    scan3_kernel<<<NBLK, 256, 0, s2>>>();
    scatter_kernel<<<(E_TOT / 4 + 255) / 256, 256, 0, s2>>>(ei);
    cudaEventRecord(evJoin, s2);

    gemm1_kernel<<<(N_NODES + 127) / 128, 256>>>(x, W1, a_src1, a_dst1);

    // join: agg1 needs the CSR
    cudaStreamWaitEvent(0, evJoin, 0);
    agg1_kernel<<<(N_NODES + 7) / 8, 256>>>(b1);

    gemm2_kernel<<<(N_NODES + 127) / 128, 256>>>(W2, a_src2, a_dst2);
    agg2_kernel<<<(N_NODES + 7) / 8, 256>>>(b2, out);
}

// round 13
// speedup vs baseline: 1.5929x; 1.1150x over previous
#include <cuda_runtime.h>
#include <cuda_bf16.h>
#include <cstdint>

#define N_NODES 50000
#define E_ORIG  800000
#define E_TOT   850000   // E_ORIG + N self-loops (both divisible by 4)
#define NBLK    196      // ceil(N_NODES/256)
#define N_HALF  25088    // 196 * 128 (gemm2 block multiple)
#define FULLMASK 0xffffffffu

// ---------------- scratch (static __device__ — no allocation) ----------------
__device__ __align__(16) int   g_srcs [E_TOT];        // src sorted by dst (CSR)
__device__ __align__(16) int   g_deg[N_NODES];
__device__ __align__(16) int   g_rowstart[N_NODES + 1];
__device__ __align__(16) int   g_cursor[N_NODES];
__device__ __align__(16) int   g_blocksum[NBLK];
__device__ __align__(16) int   g_blockoff[NBLK];
__device__ __align__(16) float g_h1  [N_NODES * 128]; // x @ W1
__device__ __align__(16) float g_as1 [N_NODES * 4];
__device__ __align__(16) float g_ad1 [N_NODES * 4];
__device__ __align__(16) float g_out1[N_NODES * 128]; // relu(agg1 + b1)
__device__ __align__(16) float g_h2  [N_NODES * 64];  // out1 @ W2
__device__ __align__(16) float g_as2 [N_NODES];
__device__ __align__(16) float g_ad2 [N_NODES];

__device__ __forceinline__ float lrelu(float v) {
    return v > 0.f ? v : 0.2f * v;
}

// packed f32x2 helpers (FFMA2 — ptxas never emits it from C++)
__device__ __forceinline__ unsigned long long pack_dup(float a) {
    unsigned long long r;
    asm("mov.b64 %0, {%1, %1};" : "=l"(r) : "f"(a));
    return r;
}
__device__ __forceinline__ void ffma2(unsigned long long& acc,
                                      unsigned long long a,
                                      unsigned long long b) {
    asm("fma.rn.f32x2 %0, %1, %2, %0;" : "+l"(acc) : "l"(a), "l"(b));
}
__device__ __forceinline__ float2 unpack2(unsigned long long v) {
    float lo, hi;
    asm("mov.b64 {%0, %1}, %2;" : "=f"(lo), "=f"(hi) : "l"(v));
    return make_float2(lo, hi);
}

// ---------------- CSR build ----------------
// edge_index is INT32 (JAX x64 disabled downcasts int64 -> int32)
__global__ void build_deg_kernel(const int* __restrict__ ei) {
    int e = (blockIdx.x * blockDim.x + threadIdx.x) * 4;
    if (e >= E_TOT) return;
    int4 d4;
    if (e < E_ORIG) {
        d4 = *(const int4*)&ei[E_ORIG + e];
    } else {
        int b = e - E_ORIG;
        d4 = make_int4(b, b + 1, b + 2, b + 3);
    }
    if ((unsigned)d4.x < (unsigned)N_NODES) atomicAdd(&g_deg[d4.x], 1);
    if ((unsigned)d4.y < (unsigned)N_NODES) atomicAdd(&g_deg[d4.y], 1);
    if ((unsigned)d4.z < (unsigned)N_NODES) atomicAdd(&g_deg[d4.z], 1);
    if ((unsigned)d4.w < (unsigned)N_NODES) atomicAdd(&g_deg[d4.w], 1);
}

// parallel scan stage 1: per-block exclusive scan (partial) + block sums
__global__ void scan1_kernel() {
    __shared__ int wsum[8], woff[8];
    int tid = threadIdx.x, lane = tid & 31, wid = tid >> 5;
    int i = blockIdx.x * 256 + tid;
    int v = (i < N_NODES) ? g_deg[i] : 0;
    int x = v;
    #pragma unroll
    for (int off = 1; off < 32; off <<= 1) {
        int t = __shfl_up_sync(FULLMASK, x, off);
        if (lane >= off) x += t;
    }
    if (lane == 31) wsum[wid] = x;
    __syncthreads();
    if (wid == 0 && lane < 8) {
        int s = wsum[lane];
        int y = s;
        #pragma unroll
        for (int off = 1; off < 8; off <<= 1) {
            int t = __shfl_up_sync(0xffu, y, off);
            if (lane >= off) y += t;
        }
        woff[lane] = y - s;
        if (lane == 7) g_blocksum[blockIdx.x] = y;
    }
    __syncthreads();
    if (i < N_NODES) g_rowstart[i] = woff[wid] + (x - v);   // partial (in-block)
}

// stage 2: single-block exclusive scan of NBLK block sums
__global__ void scan2_kernel() {
    __shared__ int wsum[8], woff[8];
    int tid = threadIdx.x, lane = tid & 31, wid = tid >> 5;
    int v = (tid < NBLK) ? g_blocksum[tid] : 0;
    int x = v;
    #pragma unroll
    for (int off = 1; off < 32; off <<= 1) {
        int t = __shfl_up_sync(FULLMASK, x, off);
        if (lane >= off) x += t;
    }
    if (lane == 31) wsum[wid] = x;
    __syncthreads();
    if (wid == 0 && lane < 8) {
        int s = wsum[lane];
        int y = s;
        #pragma unroll
        for (int off = 1; off < 8; off <<= 1) {
            int t = __shfl_up_sync(0xffu, y, off);
            if (lane >= off) y += t;
        }
        woff[lane] = y - s;
        if (lane == 7) g_rowstart[N_NODES] = y;   // total = E_TOT
    }
    __syncthreads();
    if (tid < NBLK) g_blockoff[tid] = woff[wid] + (x - v);
}

// stage 3: add block offsets -> final rowstart + cursor
__global__ void scan3_kernel() {
    int i = blockIdx.x * 256 + threadIdx.x;
    if (i < N_NODES) {
        int r = g_rowstart[i] + g_blockoff[blockIdx.x];
        g_rowstart[i] = r;
        g_cursor[i] = r;
    }
}

__global__ void scatter_kernel(const int* __restrict__ ei) {
    int e = (blockIdx.x * blockDim.x + threadIdx.x) * 4;
    if (e >= E_TOT) return;
    int4 s4, d4;
    if (e < E_ORIG) {
        s4 = *(const int4*)&ei[e];
        d4 = *(const int4*)&ei[E_ORIG + e];
    } else {
        int b = e - E_ORIG;
        s4 = make_int4(b, b + 1, b + 2, b + 3);
        d4 = s4;
    }
    #pragma unroll
    for (int l = 0; l < 4; l++) {
        int d = (l == 0) ? d4.x : (l == 1) ? d4.y : (l == 2) ? d4.z : d4.w;
        int s = (l == 0) ? s4.x : (l == 1) ? s4.y : (l == 2) ? s4.z : s4.w;
        if ((unsigned)d < (unsigned)N_NODES) {
            int pos = atomicAdd(&g_cursor[d], 1);
            if ((unsigned)pos < (unsigned)E_TOT) g_srcs[pos] = s;
        }
    }
}

// ---- GEMM1: h1 = x @ W1 (FFMA2, sw-pipelined) + fused alpha1 epilogue ------
__global__ __launch_bounds__(256, 2) void gemm1_kernel(const float* __restrict__ X,
                                                       const float* __restrict__ W,
                                                       const float* __restrict__ a_src,
                                                       const float* __restrict__ a_dst) {
    __shared__ __align__(16) float As[16][132];
    __shared__ __align__(16) float Bs[16][128];
    int tid = threadIdx.x;
    int tx = tid & 15, ty = tid >> 4;
    int blockRow = blockIdx.x * 128;
    unsigned long long accp[8][4];
    #pragma unroll
    for (int i = 0; i < 8; i++)
        #pragma unroll
        for (int j = 0; j < 4; j++) accp[i][j] = 0ull;

    int id0 = tid * 2, id1 = tid * 2 + 1;
    int xr0 = id0 >> 2, xc0 = (id0 & 3) * 4;
    int xr1 = id1 >> 2, xc1 = (id1 & 3) * 4;
    int wr0 = id0 >> 5, wc0 = (id0 & 31) * 4;
    int wr1 = id1 >> 5, wc1 = (id1 & 31) * 4;
    int grow0 = blockRow + xr0, grow1 = blockRow + xr1;

    float4 xa0 = make_float4(0, 0, 0, 0), xa1 = make_float4(0, 0, 0, 0);
    if (grow0 < N_NODES) xa0 = *(const float4*)&X[grow0 * 128 + xc0];
    if (grow1 < N_NODES) xa1 = *(const float4*)&X[grow1 * 128 + xc1];
    float4 wb0 = *(const float4*)&W[wr0 * 128 + wc0];
    float4 wb1 = *(const float4*)&W[wr1 * 128 + wc1];

    for (int k0 = 0; k0 < 128; k0 += 16) {
        As[xc0 + 0][xr0] = xa0.x; As[xc0 + 1][xr0] = xa0.y;
        As[xc0 + 2][xr0] = xa0.z; As[xc0 + 3][xr0] = xa0.w;
        As[xc1 + 0][xr1] = xa1.x; As[xc1 + 1][xr1] = xa1.y;
        As[xc1 + 2][xr1] = xa1.z; As[xc1 + 3][xr1] = xa1.w;
        *(float4*)&Bs[wr0][wc0] = wb0;
        *(float4*)&Bs[wr1][wc1] = wb1;
        __syncthreads();
        if (k0 + 16 < 128) {   // prefetch next tile while computing this one
            int kn = k0 + 16;
            if (grow0 < N_NODES) xa0 = *(const float4*)&X[grow0 * 128 + kn + xc0];
            if (grow1 < N_NODES) xa1 = *(const float4*)&X[grow1 * 128 + kn + xc1];
            wb0 = *(const float4*)&W[(kn + wr0) * 128 + wc0];
            wb1 = *(const float4*)&W[(kn + wr1) * 128 + wc1];
        }
        #pragma unroll
        for (int k = 0; k < 16; k++) {
            float a[8];
            *(float4*)&a[0] = *(const float4*)&As[k][ty * 4];
            *(float4*)&a[4] = *(const float4*)&As[k][64 + ty * 4];
            unsigned long long bp[4];
            bp[0] = *(const unsigned long long*)&Bs[k][tx * 4];
            bp[1] = *(const unsigned long long*)&Bs[k][tx * 4 + 2];
            bp[2] = *(const unsigned long long*)&Bs[k][64 + tx * 4];
            bp[3] = *(const unsigned long long*)&Bs[k][64 + tx * 4 + 2];
            #pragma unroll
            for (int i = 0; i < 8; i++) {
                unsigned long long ap = pack_dup(a[i]);
                #pragma unroll
                for (int j = 0; j < 4; j++) ffma2(accp[i][j], ap, bp[j]);
            }
        }
        __syncthreads();
    }

    float asl[4], adl[4], ash[4], adh[4];
    #pragma unroll
    for (int j = 0; j < 4; j++) {
        asl[j] = a_src[tx * 4 + j];      adl[j] = a_dst[tx * 4 + j];
        ash[j] = a_src[64 + tx * 4 + j]; adh[j] = a_dst[64 + tx * 4 + j];
    }
    #pragma unroll
    for (int i = 0; i < 8; i++) {
        int gr = blockRow + ((i < 4) ? (ty * 4 + i) : (64 + ty * 4 + i - 4));
        if (gr >= N_NODES) continue;
        float2 p0 = unpack2(accp[i][0]), p1 = unpack2(accp[i][1]);
        float2 p2 = unpack2(accp[i][2]), p3 = unpack2(accp[i][3]);
        *(float4*)&g_h1[gr * 128 + tx * 4]      = make_float4(p0.x, p0.y, p1.x, p1.y);
        *(float4*)&g_h1[gr * 128 + 64 + tx * 4] = make_float4(p2.x, p2.y, p3.x, p3.y);
        float sl = p0.x * asl[0] + p0.y * asl[1] + p1.x * asl[2] + p1.y * asl[3];
        float dl = p0.x * adl[0] + p0.y * adl[1] + p1.x * adl[2] + p1.y * adl[3];
        float sh = p2.x * ash[0] + p2.y * ash[1] + p3.x * ash[2] + p3.y * ash[3];
        float dh = p2.x * adh[0] + p2.y * adh[1] + p3.x * adh[2] + p3.y * adh[3];
        #pragma unroll
        for (int off = 1; off <= 4; off <<= 1) {
            sl += __shfl_xor_sync(FULLMASK, sl, off);
            dl += __shfl_xor_sync(FULLMASK, dl, off);
            sh += __shfl_xor_sync(FULLMASK, sh, off);
            dh += __shfl_xor_sync(FULLMASK, dh, off);
        }
        if ((tx & 7) == 0) {
            int hl = tx >> 3;
            g_as1[gr * 4 + hl] = sl;       g_ad1[gr * 4 + hl] = dl;
            g_as1[gr * 4 + 2 + hl] = sh;   g_ad1[gr * 4 + 2 + hl] = dh;
        }
    }
}

// ---- layer-1 aggregation: warp per dst node; lane owns 4 consecutive cols --
__global__ __launch_bounds__(256) void agg1_kernel(const float* __restrict__ b1,
                                                   int node0, int nnodes) {
    __shared__ float sw[8][2][32][4];   // per-edge per-head weights
    __shared__ int   ss[8][2][32];
    int warpid = threadIdx.x >> 5;
    int lane = threadIdx.x & 31;
    int n = node0 + blockIdx.x * 8 + warpid;
    if (n >= node0 + nnodes) return;
    int s0 = g_rowstart[n], s1 = g_rowstart[n + 1];
    float4 ad = *(const float4*)&g_ad1[n * 4];

    // fused max+denom (online softmax)
    float m0 = -1e30f, m1 = -1e30f, m2 = -1e30f, m3 = -1e30f;
    float d0 = 0.f, d1 = 0.f, d2 = 0.f, d3 = 0.f;
    for (int e = s0 + lane; e < s1; e += 32) {
        int s = g_srcs[e];
        float4 a = *(const float4*)&g_as1[s * 4];
        float e0 = lrelu(a.x + ad.x), e1 = lrelu(a.y + ad.y);
        float e2 = lrelu(a.z + ad.z), e3 = lrelu(a.w + ad.w);
        float nm;
        nm = fmaxf(m0, e0); d0 = d0 * __expf(m0 - nm) + __expf(e0 - nm); m0 = nm;
        nm = fmaxf(m1, e1); d1 = d1 * __expf(m1 - nm) + __expf(e1 - nm); m1 = nm;
        nm = fmaxf(m2, e2); d2 = d2 * __expf(m2 - nm) + __expf(e2 - nm); m2 = nm;
        nm = fmaxf(m3, e3); d3 = d3 * __expf(m3 - nm) + __expf(e3 - nm); m3 = nm;
    }
    #pragma unroll
    for (int off = 16; off >= 1; off >>= 1) {
        float om, od, nm;
        om = __shfl_xor_sync(FULLMASK, m0, off); od = __shfl_xor_sync(FULLMASK, d0, off);
        nm = fmaxf(m0, om); d0 = d0 * __expf(m0 - nm) + od * __expf(om - nm); m0 = nm;
        om = __shfl_xor_sync(FULLMASK, m1, off); od = __shfl_xor_sync(FULLMASK, d1, off);
        nm = fmaxf(m1, om); d1 = d1 * __expf(m1 - nm) + od * __expf(om - nm); m1 = nm;
        om = __shfl_xor_sync(FULLMASK, m2, off); od = __shfl_xor_sync(FULLMASK, d2, off);
        nm = fmaxf(m2, om); d2 = d2 * __expf(m2 - nm) + od * __expf(om - nm); m2 = nm;
        om = __shfl_xor_sync(FULLMASK, m3, off); od = __shfl_xor_sync(FULLMASK, d3, off);
        nm = fmaxf(m3, om); d3 = d3 * __expf(m3 - nm) + od * __expf(om - nm); m3 = nm;
    }
    float r0 = 1.f / d0, r1 = 1.f / d1, r2 = 1.f / d2, r3 = 1.f / d3;

    // weighted accumulate: lane owns cols [4*lane, 4*lane+4) — ONE LDG.128/edge
    float acc0 = 0.f, acc1 = 0.f, acc2 = 0.f, acc3 = 0.f;
    int hsel = lane >> 3;                 // head index for this lane's cols
    int buf = 0;
    {
        int e = s0 + lane;
        if (e < s1) {
            int sl = g_srcs[e];
            float4 a = *(const float4*)&g_as1[sl * 4];
            sw[warpid][0][lane][0] = __expf(lrelu(a.x + ad.x) - m0) * r0;
            sw[warpid][0][lane][1] = __expf(lrelu(a.y + ad.y) - m1) * r1;
            sw[warpid][0][lane][2] = __expf(lrelu(a.z + ad.z) - m2) * r2;
            sw[warpid][0][lane][3] = __expf(lrelu(a.w + ad.w) - m3) * r3;
            ss[warpid][0][lane] = sl;
        }
    }
    __syncwarp();
    for (int base = s0; base < s1; base += 32) {
        int nb = base + 32;
        if (nb < s1) {
            int e = nb + lane;
            if (e < s1) {
                int sl = g_srcs[e];
                float4 a = *(const float4*)&g_as1[sl * 4];
                sw[warpid][buf ^ 1][lane][0] = __expf(lrelu(a.x + ad.x) - m0) * r0;
                sw[warpid][buf ^ 1][lane][1] = __expf(lrelu(a.y + ad.y) - m1) * r1;
                sw[warpid][buf ^ 1][lane][2] = __expf(lrelu(a.z + ad.z) - m2) * r2;
                sw[warpid][buf ^ 1][lane][3] = __expf(lrelu(a.w + ad.w) - m3) * r3;
                ss[warpid][buf ^ 1][lane] = sl;
            }
        }
        int cnt = min(32, s1 - base);
        #pragma unroll 4
        for (int j = 0; j < cnt; j++) {
            int s = ss[warpid][buf][j];
            float wsel = sw[warpid][buf][j][hsel];
            float4 h = *(const float4*)&g_h1[s * 128 + lane * 4];
            acc0 = fmaf(h.x, wsel, acc0);
            acc1 = fmaf(h.y, wsel, acc1);
            acc2 = fmaf(h.z, wsel, acc2);
            acc3 = fmaf(h.w, wsel, acc3);
        }
        __syncwarp();
        buf ^= 1;
    }
    float4 bb = *(const float4*)&b1[lane * 4];
    *(float4*)&g_out1[n * 128 + lane * 4] =
        make_float4(fmaxf(acc0 + bb.x, 0.f), fmaxf(acc1 + bb.y, 0.f),
                    fmaxf(acc2 + bb.z, 0.f), fmaxf(acc3 + bb.w, 0.f));
}

// ---- GEMM2: h2 = out1 @ W2 (FFMA2, sw-pipelined) + fused alpha2 epilogue ---
__global__ __launch_bounds__(256, 2) void gemm2_kernel(const float* __restrict__ W,
                                                       const float* __restrict__ a_src,
                                                       const float* __restrict__ a_dst,
                                                       int rowBase) {
    __shared__ __align__(16) float As[16][132];
    __shared__ __align__(16) float Bs[16][64];
    int tid = threadIdx.x;
    int tx = tid & 15, ty = tid >> 4;
    int blockRow = rowBase + blockIdx.x * 128;
    unsigned long long accp[8][2];
    #pragma unroll
    for (int i = 0; i < 8; i++) { accp[i][0] = 0ull; accp[i][1] = 0ull; }

    int id0 = tid * 2, id1 = tid * 2 + 1;
    int xr0 = id0 >> 2, xc0 = (id0 & 3) * 4;
    int xr1 = id1 >> 2, xc1 = (id1 & 3) * 4;
    int wr = tid >> 4, wc = (tid & 15) * 4;
    int grow0 = blockRow + xr0, grow1 = blockRow + xr1;

    float4 xa0 = make_float4(0, 0, 0, 0), xa1 = make_float4(0, 0, 0, 0);
    if (grow0 < N_NODES) xa0 = *(const float4*)&g_out1[grow0 * 128 + xc0];
    if (grow1 < N_NODES) xa1 = *(const float4*)&g_out1[grow1 * 128 + xc1];
    float4 wb = *(const float4*)&W[wr * 64 + wc];

    for (int k0 = 0; k0 < 128; k0 += 16) {
        As[xc0 + 0][xr0] = xa0.x; As[xc0 + 1][xr0] = xa0.y;
        As[xc0 + 2][xr0] = xa0.z; As[xc0 + 3][xr0] = xa0.w;
        As[xc1 + 0][xr1] = xa1.x; As[xc1 + 1][xr1] = xa1.y;
        As[xc1 + 2][xr1] = xa1.z; As[xc1 + 3][xr1] = xa1.w;
        *(float4*)&Bs[wr][wc] = wb;
        __syncthreads();
        if (k0 + 16 < 128) {
            int kn = k0 + 16;
            if (grow0 < N_NODES) xa0 = *(const float4*)&g_out1[grow0 * 128 + kn + xc0];
            if (grow1 < N_NODES) xa1 = *(const float4*)&g_out1[grow1 * 128 + kn + xc1];
            wb = *(const float4*)&W[(kn + wr) * 64 + wc];
        }
        #pragma unroll
        for (int k = 0; k < 16; k++) {
            float a[8];
            *(float4*)&a[0] = *(const float4*)&As[k][ty * 4];
            *(float4*)&a[4] = *(const float4*)&As[k][64 + ty * 4];
            unsigned long long bp[2];
            bp[0] = *(const unsigned long long*)&Bs[k][tx * 4];
            bp[1] = *(const unsigned long long*)&Bs[k][tx * 4 + 2];
            #pragma unroll
            for (int i = 0; i < 8; i++) {
                unsigned long long ap = pack_dup(a[i]);
                ffma2(accp[i][0], ap, bp[0]);
                ffma2(accp[i][1], ap, bp[1]);
            }
        }
        __syncthreads();
    }

    float as4[4], ad4[4];
    #pragma unroll
    for (int j = 0; j < 4; j++) {
        as4[j] = a_src[tx * 4 + j];
        ad4[j] = a_dst[tx * 4 + j];
    }
    #pragma unroll
    for (int i = 0; i < 8; i++) {
        int gr = blockRow + ((i < 4) ? (ty * 4 + i) : (64 + ty * 4 + i - 4));
        if (gr >= N_NODES) continue;
        float2 p0 = unpack2(accp[i][0]), p1 = unpack2(accp[i][1]);
        *(float4*)&g_h2[gr * 64 + tx * 4] = make_float4(p0.x, p0.y, p1.x, p1.y);
        float ps = p0.x * as4[0] + p0.y * as4[1] + p1.x * as4[2] + p1.y * as4[3];
        float pd = p0.x * ad4[0] + p0.y * ad4[1] + p1.x * ad4[2] + p1.y * ad4[3];
        #pragma unroll
        for (int off = 1; off <= 8; off <<= 1) {
            ps += __shfl_xor_sync(FULLMASK, ps, off);
            pd += __shfl_xor_sync(FULLMASK, pd, off);
        }
        if (tx == 0) { g_as2[gr] = ps; g_ad2[gr] = pd; }
    }
}

// ---- layer-2 aggregation: warp per dst node; lane owns 2 consecutive cols --
__global__ __launch_bounds__(256) void agg2_kernel(const float* __restrict__ b2,
                                                   float* __restrict__ out) {
    __shared__ float sw[8][2][32];
    __shared__ int   ss[8][2][32];
    int warpid = threadIdx.x >> 5;
    int lane = threadIdx.x & 31;
    int n = blockIdx.x * 8 + warpid;
    if (n >= N_NODES) return;
    int s0 = g_rowstart[n], s1 = g_rowstart[n + 1];
    float ad = g_ad2[n];

    float m = -1e30f, d = 0.f;
    for (int e = s0 + lane; e < s1; e += 32) {
        float ev = lrelu(g_as2[g_srcs[e]] + ad);
        float nm = fmaxf(m, ev);
        d = d * __expf(m - nm) + __expf(ev - nm);
        m = nm;
    }
    #pragma unroll
    for (int off = 16; off >= 1; off >>= 1) {
        float om = __shfl_xor_sync(FULLMASK, m, off);
        float od = __shfl_xor_sync(FULLMASK, d, off);
        float nm = fmaxf(m, om);
        d = d * __expf(m - nm) + od * __expf(om - nm);
        m = nm;
    }
    float rd = 1.f / d;

    float acc0 = 0.f, acc1 = 0.f;
    int buf = 0;
    {
        int e = s0 + lane;
        if (e < s1) {
            int sl = g_srcs[e];
            sw[warpid][0][lane] = __expf(lrelu(g_as2[sl] + ad) - m) * rd;
            ss[warpid][0][lane] = sl;
        }
    }
    __syncwarp();
    for (int base = s0; base < s1; base += 32) {
        int nb = base + 32;
        if (nb < s1) {
            int e = nb + lane;
            if (e < s1) {
                int sl = g_srcs[e];
                sw[warpid][buf ^ 1][lane] = __expf(lrelu(g_as2[sl] + ad) - m) * rd;
                ss[warpid][buf ^ 1][lane] = sl;
            }
        }
        int cnt = min(32, s1 - base);
        #pragma unroll 4
        for (int j = 0; j < cnt; j++) {
            float wj = sw[warpid][buf][j];
            int s = ss[warpid][buf][j];
            float2 h = *(const float2*)&g_h2[s * 64 + lane * 2];
            acc0 = fmaf(h.x, wj, acc0);
            acc1 = fmaf(h.y, wj, acc1);
        }
        __syncwarp();
        buf ^= 1;
    }
    float2 bb = *(const float2*)&b2[lane * 2];
    *(float2*)&out[n * 64 + lane * 2] = make_float2(acc0 + bb.x, acc1 + bb.y);
}

// ---------------- launcher ----------------
extern "C" void kernel_launch(void* const* d_in, const int* in_sizes, int n_in,
                              void* d_out, int out_size) {
    const float* x      = (const float*)d_in[0];
    const int*   ei     = (const int*)d_in[1];   // int32 (JAX x64 disabled)
    // d_in[2] edge_weight unused (PyG GATConv ignores it with edge_dim unset)
    const float* W1     = (const float*)d_in[3];
    const float* a_src1 = (const float*)d_in[4];
    const float* a_dst1 = (const float*)d_in[5];
    const float* b1     = (const float*)d_in[6];
    const float* W2     = (const float*)d_in[7];
    const float* a_src2 = (const float*)d_in[8];
    const float* a_dst2 = (const float*)d_in[9];
    const float* b2     = (const float*)d_in[10];
    float*       out    = (float*)d_out;

    static cudaStream_t s2 = nullptr;
    static cudaEvent_t evFork = nullptr, evJoin = nullptr, evA = nullptr, evG2a = nullptr;
    static void* degPtr = nullptr;
    if (s2 == nullptr) {
        cudaStreamCreateWithFlags(&s2, cudaStreamNonBlocking);
        cudaEventCreateWithFlags(&evFork, cudaEventDisableTiming);
        cudaEventCreateWithFlags(&evJoin, cudaEventDisableTiming);
        cudaEventCreateWithFlags(&evA, cudaEventDisableTiming);
        cudaEventCreateWithFlags(&evG2a, cudaEventDisableTiming);
        cudaGetSymbolAddress(&degPtr, g_deg);
    }

    // fork: CSR build on side stream, overlapped with GEMM1
    cudaEventRecord(evFork, 0);
    cudaStreamWaitEvent(s2, evFork, 0);
    cudaMemsetAsync(degPtr, 0, N_NODES * sizeof(int), s2);
    build_deg_kernel<<<(E_TOT / 4 + 255) / 256, 256, 0, s2>>>(ei);
    scan1_kernel<<<NBLK, 256, 0, s2>>>();
    scan2_kernel<<<1, 256, 0, s2>>>();
    scan3_kernel<<<NBLK, 256, 0, s2>>>();
    scatter_kernel<<<(E_TOT / 4 + 255) / 256, 256, 0, s2>>>(ei);
    cudaEventRecord(evJoin, s2);

    gemm1_kernel<<<(N_NODES + 127) / 128, 256>>>(x, W1, a_src1, a_dst1);

    // join: agg1 needs the CSR
    cudaStreamWaitEvent(0, evJoin, 0);

    // agg1 half A -> (side stream) gemm2 half A overlapped with agg1 half B
    agg1_kernel<<<N_HALF / 8, 256>>>(b1, 0, N_HALF);
    cudaEventRecord(evA, 0);
    agg1_kernel<<<(N_NODES - N_HALF + 7) / 8, 256>>>(b1, N_HALF, N_NODES - N_HALF);

    cudaStreamWaitEvent(s2, evA, 0);
    gemm2_kernel<<<N_HALF / 128, 256, 0, s2>>>(W2, a_src2, a_dst2, 0);
    cudaEventRecord(evG2a, s2);

    gemm2_kernel<<<(N_NODES - N_HALF + 127) / 128, 256>>>(W2, a_src2, a_dst2, N_HALF);

    // agg2 needs both gemm2 halves
    cudaStreamWaitEvent(0, evG2a, 0);
    agg2_kernel<<<(N_NODES + 7) / 8, 256>>>(b2, out);
}

// round 15
// speedup vs baseline: 1.6849x; 1.0577x over previous
#include <cuda_runtime.h>
#include <cuda_bf16.h>
#include <cuda_fp16.h>
#include <cstdint>

#define N_NODES 50000
#define E_ORIG  800000
#define E_TOT   850000   // E_ORIG + N self-loops (both divisible by 4)
#define NBLK    196      // ceil(N_NODES/256)
#define N_HALF  25088    // 196 * 128 (gemm2 block multiple)
#define FULLMASK 0xffffffffu

// ---------------- scratch (static __device__ — no allocation) ----------------
__device__ __align__(16) int   g_srcs [E_TOT];        // src sorted by dst (CSR)
__device__ __align__(16) int   g_deg[N_NODES];
__device__ __align__(16) int   g_rowstart[N_NODES + 1];
__device__ __align__(16) int   g_cursor[N_NODES];
__device__ __align__(16) int   g_blocksum[NBLK];
__device__ __align__(16) int   g_blockoff[NBLK];
__device__ __align__(16) __half g_h1h[N_NODES * 128]; // fp16 mirror of x @ W1 (gather only)
__device__ __align__(16) float g_as1 [N_NODES * 4];
__device__ __align__(16) float g_ad1 [N_NODES * 4];
__device__ __align__(16) float g_out1[N_NODES * 128]; // relu(agg1 + b1)
__device__ __align__(16) __half g_h2h[N_NODES * 64];  // fp16 mirror of out1 @ W2
__device__ __align__(16) float g_as2 [N_NODES];
__device__ __align__(16) float g_ad2 [N_NODES];

__device__ __forceinline__ float lrelu(float v) {
    return v > 0.f ? v : 0.2f * v;
}

// packed f32x2 helpers (FFMA2 — ptxas never emits it from C++)
__device__ __forceinline__ unsigned long long pack_dup(float a) {
    unsigned long long r;
    asm("mov.b64 %0, {%1, %1};" : "=l"(r) : "f"(a));
    return r;
}
__device__ __forceinline__ void ffma2(unsigned long long& acc,
                                      unsigned long long a,
                                      unsigned long long b) {
    asm("fma.rn.f32x2 %0, %1, %2, %0;" : "+l"(acc) : "l"(a), "l"(b));
}
__device__ __forceinline__ float2 unpack2(unsigned long long v) {
    float lo, hi;
    asm("mov.b64 {%0, %1}, %2;" : "=f"(lo), "=f"(hi) : "l"(v));
    return make_float2(lo, hi);
}
__device__ __forceinline__ uint32_t h2_bits(__half2 h) {
    uint32_t u;
    memcpy(&u, &h, 4);
    return u;
}

// ---------------- CSR build ----------------
// edge_index is INT32 (JAX x64 disabled downcasts int64 -> int32)
__global__ void build_deg_kernel(const int* __restrict__ ei) {
    int e = (blockIdx.x * blockDim.x + threadIdx.x) * 4;
    if (e >= E_TOT) return;
    int4 d4;
    if (e < E_ORIG) {
        d4 = *(const int4*)&ei[E_ORIG + e];
    } else {
        int b = e - E_ORIG;
        d4 = make_int4(b, b + 1, b + 2, b + 3);
    }
    if ((unsigned)d4.x < (unsigned)N_NODES) atomicAdd(&g_deg[d4.x], 1);
    if ((unsigned)d4.y < (unsigned)N_NODES) atomicAdd(&g_deg[d4.y], 1);
    if ((unsigned)d4.z < (unsigned)N_NODES) atomicAdd(&g_deg[d4.z], 1);
    if ((unsigned)d4.w < (unsigned)N_NODES) atomicAdd(&g_deg[d4.w], 1);
}

// parallel scan stage 1: per-block exclusive scan (partial) + block sums
__global__ void scan1_kernel() {
    __shared__ int wsum[8], woff[8];
    int tid = threadIdx.x, lane = tid & 31, wid = tid >> 5;
    int i = blockIdx.x * 256 + tid;
    int v = (i < N_NODES) ? g_deg[i] : 0;
    int x = v;
    #pragma unroll
    for (int off = 1; off < 32; off <<= 1) {
        int t = __shfl_up_sync(FULLMASK, x, off);
        if (lane >= off) x += t;
    }
    if (lane == 31) wsum[wid] = x;
    __syncthreads();
    if (wid == 0 && lane < 8) {
        int s = wsum[lane];
        int y = s;
        #pragma unroll
        for (int off = 1; off < 8; off <<= 1) {
            int t = __shfl_up_sync(0xffu, y, off);
            if (lane >= off) y += t;
        }
        woff[lane] = y - s;
        if (lane == 7) g_blocksum[blockIdx.x] = y;
    }
    __syncthreads();
    if (i < N_NODES) g_rowstart[i] = woff[wid] + (x - v);   // partial (in-block)
}

// stage 2: single-block exclusive scan of NBLK block sums
__global__ void scan2_kernel() {
    __shared__ int wsum[8], woff[8];
    int tid = threadIdx.x, lane = tid & 31, wid = tid >> 5;
    int v = (tid < NBLK) ? g_blocksum[tid] : 0;
    int x = v;
    #pragma unroll
    for (int off = 1; off < 32; off <<= 1) {
        int t = __shfl_up_sync(FULLMASK, x, off);
        if (lane >= off) x += t;
    }
    if (lane == 31) wsum[wid] = x;
    __syncthreads();
    if (wid == 0 && lane < 8) {
        int s = wsum[lane];
        int y = s;
        #pragma unroll
        for (int off = 1; off < 8; off <<= 1) {
            int t = __shfl_up_sync(0xffu, y, off);
            if (lane >= off) y += t;
        }
        woff[lane] = y - s;
        if (lane == 7) g_rowstart[N_NODES] = y;   // total = E_TOT
    }
    __syncthreads();
    if (tid < NBLK) g_blockoff[tid] = woff[wid] + (x - v);
}

// stage 3: add block offsets -> final rowstart + cursor
__global__ void scan3_kernel() {
    int i = blockIdx.x * 256 + threadIdx.x;
    if (i < N_NODES) {
        int r = g_rowstart[i] + g_blockoff[blockIdx.x];
        g_rowstart[i] = r;
        g_cursor[i] = r;
    }
}

__global__ void scatter_kernel(const int* __restrict__ ei) {
    int e = (blockIdx.x * blockDim.x + threadIdx.x) * 4;
    if (e >= E_TOT) return;
    int4 s4, d4;
    if (e < E_ORIG) {
        s4 = *(const int4*)&ei[e];
        d4 = *(const int4*)&ei[E_ORIG + e];
    } else {
        int b = e - E_ORIG;
        s4 = make_int4(b, b + 1, b + 2, b + 3);
        d4 = s4;
    }
    #pragma unroll
    for (int l = 0; l < 4; l++) {
        int d = (l == 0) ? d4.x : (l == 1) ? d4.y : (l == 2) ? d4.z : d4.w;
        int s = (l == 0) ? s4.x : (l == 1) ? s4.y : (l == 2) ? s4.z : s4.w;
        if ((unsigned)d < (unsigned)N_NODES) {
            int pos = atomicAdd(&g_cursor[d], 1);
            if ((unsigned)pos < (unsigned)E_TOT) g_srcs[pos] = s;
        }
    }
}

// ---- GEMM1: h1 = x @ W1 (FFMA2, sw-pipelined) + fused alpha1 + fp16 mirror -
__global__ __launch_bounds__(256, 2) void gemm1_kernel(const float* __restrict__ X,
                                                       const float* __restrict__ W,
                                                       const float* __restrict__ a_src,
                                                       const float* __restrict__ a_dst) {
    __shared__ __align__(16) float As[16][132];
    __shared__ __align__(16) float Bs[16][128];
    int tid = threadIdx.x;
    int tx = tid & 15, ty = tid >> 4;
    int blockRow = blockIdx.x * 128;
    unsigned long long accp[8][4];
    #pragma unroll
    for (int i = 0; i < 8; i++)
        #pragma unroll
        for (int j = 0; j < 4; j++) accp[i][j] = 0ull;

    int id0 = tid * 2, id1 = tid * 2 + 1;
    int xr0 = id0 >> 2, xc0 = (id0 & 3) * 4;
    int xr1 = id1 >> 2, xc1 = (id1 & 3) * 4;
    int wr0 = id0 >> 5, wc0 = (id0 & 31) * 4;
    int wr1 = id1 >> 5, wc1 = (id1 & 31) * 4;
    int grow0 = blockRow + xr0, grow1 = blockRow + xr1;

    float4 xa0 = make_float4(0, 0, 0, 0), xa1 = make_float4(0, 0, 0, 0);
    if (grow0 < N_NODES) xa0 = *(const float4*)&X[grow0 * 128 + xc0];
    if (grow1 < N_NODES) xa1 = *(const float4*)&X[grow1 * 128 + xc1];
    float4 wb0 = *(const float4*)&W[wr0 * 128 + wc0];
    float4 wb1 = *(const float4*)&W[wr1 * 128 + wc1];

    for (int k0 = 0; k0 < 128; k0 += 16) {
        As[xc0 + 0][xr0] = xa0.x; As[xc0 + 1][xr0] = xa0.y;
        As[xc0 + 2][xr0] = xa0.z; As[xc0 + 3][xr0] = xa0.w;
        As[xc1 + 0][xr1] = xa1.x; As[xc1 + 1][xr1] = xa1.y;
        As[xc1 + 2][xr1] = xa1.z; As[xc1 + 3][xr1] = xa1.w;
        *(float4*)&Bs[wr0][wc0] = wb0;
        *(float4*)&Bs[wr1][wc1] = wb1;
        __syncthreads();
        if (k0 + 16 < 128) {   // prefetch next tile while computing this one
            int kn = k0 + 16;
            if (grow0 < N_NODES) xa0 = *(const float4*)&X[grow0 * 128 + kn + xc0];
            if (grow1 < N_NODES) xa1 = *(const float4*)&X[grow1 * 128 + kn + xc1];
            wb0 = *(const float4*)&W[(kn + wr0) * 128 + wc0];
            wb1 = *(const float4*)&W[(kn + wr1) * 128 + wc1];
        }
        #pragma unroll
        for (int k = 0; k < 16; k++) {
            float a[8];
            *(float4*)&a[0] = *(const float4*)&As[k][ty * 4];
            *(float4*)&a[4] = *(const float4*)&As[k][64 + ty * 4];
            unsigned long long bp[4];
            bp[0] = *(const unsigned long long*)&Bs[k][tx * 4];
            bp[1] = *(const unsigned long long*)&Bs[k][tx * 4 + 2];
            bp[2] = *(const unsigned long long*)&Bs[k][64 + tx * 4];
            bp[3] = *(const unsigned long long*)&Bs[k][64 + tx * 4 + 2];
            #pragma unroll
            for (int i = 0; i < 8; i++) {
                unsigned long long ap = pack_dup(a[i]);
                #pragma unroll
                for (int j = 0; j < 4; j++) ffma2(accp[i][j], ap, bp[j]);
            }
        }
        __syncthreads();
    }

    float asl[4], adl[4], ash[4], adh[4];
    #pragma unroll
    for (int j = 0; j < 4; j++) {
        asl[j] = a_src[tx * 4 + j];      adl[j] = a_dst[tx * 4 + j];
        ash[j] = a_src[64 + tx * 4 + j]; adh[j] = a_dst[64 + tx * 4 + j];
    }
    #pragma unroll
    for (int i = 0; i < 8; i++) {
        int gr = blockRow + ((i < 4) ? (ty * 4 + i) : (64 + ty * 4 + i - 4));
        if (gr >= N_NODES) continue;
        float2 p0 = unpack2(accp[i][0]), p1 = unpack2(accp[i][1]);
        float2 p2 = unpack2(accp[i][2]), p3 = unpack2(accp[i][3]);
        // fp16 mirror for the agg1 gather (only consumer of h1)
        __half2 q0 = __floats2half2_rn(p0.x, p0.y);
        __half2 q1 = __floats2half2_rn(p1.x, p1.y);
        __half2 q2 = __floats2half2_rn(p2.x, p2.y);
        __half2 q3 = __floats2half2_rn(p3.x, p3.y);
        *(uint2*)&g_h1h[gr * 128 + tx * 4]      = make_uint2(h2_bits(q0), h2_bits(q1));
        *(uint2*)&g_h1h[gr * 128 + 64 + tx * 4] = make_uint2(h2_bits(q2), h2_bits(q3));
        float sl = p0.x * asl[0] + p0.y * asl[1] + p1.x * asl[2] + p1.y * asl[3];
        float dl = p0.x * adl[0] + p0.y * adl[1] + p1.x * adl[2] + p1.y * adl[3];
        float sh = p2.x * ash[0] + p2.y * ash[1] + p3.x * ash[2] + p3.y * ash[3];
        float dh = p2.x * adh[0] + p2.y * adh[1] + p3.x * adh[2] + p3.y * adh[3];
        #pragma unroll
        for (int off = 1; off <= 4; off <<= 1) {
            sl += __shfl_xor_sync(FULLMASK, sl, off);
            dl += __shfl_xor_sync(FULLMASK, dl, off);
            sh += __shfl_xor_sync(FULLMASK, sh, off);
            dh += __shfl_xor_sync(FULLMASK, dh, off);
        }
        if ((tx & 7) == 0) {
            int hl = tx >> 3;
            g_as1[gr * 4 + hl] = sl;       g_ad1[gr * 4 + hl] = dl;
            g_as1[gr * 4 + 2 + hl] = sh;   g_ad1[gr * 4 + 2 + hl] = dh;
        }
    }
}

// ---- layer-1 aggregation: warp per dst node; fp16 gather (1 LDG.64/edge) ---
__global__ __launch_bounds__(256) void agg1_kernel(const float* __restrict__ b1,
                                                   int node0, int nnodes) {
    __shared__ float sw[8][2][32][4];   // per-edge per-head weights
    __shared__ int   ss[8][2][32];
    int warpid = threadIdx.x >> 5;
    int lane = threadIdx.x & 31;
    int n = node0 + blockIdx.x * 8 + warpid;
    if (n >= node0 + nnodes) return;
    int s0 = g_rowstart[n], s1 = g_rowstart[n + 1];
    float4 ad = *(const float4*)&g_ad1[n * 4];

    // fused max+denom (online softmax)
    float m0 = -1e30f, m1 = -1e30f, m2 = -1e30f, m3 = -1e30f;
    float d0 = 0.f, d1 = 0.f, d2 = 0.f, d3 = 0.f;
    for (int e = s0 + lane; e < s1; e += 32) {
        int s = g_srcs[e];
        float4 a = *(const float4*)&g_as1[s * 4];
        float e0 = lrelu(a.x + ad.x), e1 = lrelu(a.y + ad.y);
        float e2 = lrelu(a.z + ad.z), e3 = lrelu(a.w + ad.w);
        float nm;
        nm = fmaxf(m0, e0); d0 = d0 * __expf(m0 - nm) + __expf(e0 - nm); m0 = nm;
        nm = fmaxf(m1, e1); d1 = d1 * __expf(m1 - nm) + __expf(e1 - nm); m1 = nm;
        nm = fmaxf(m2, e2); d2 = d2 * __expf(m2 - nm) + __expf(e2 - nm); m2 = nm;
        nm = fmaxf(m3, e3); d3 = d3 * __expf(m3 - nm) + __expf(e3 - nm); m3 = nm;
    }
    #pragma unroll
    for (int off = 16; off >= 1; off >>= 1) {
        float om, od, nm;
        om = __shfl_xor_sync(FULLMASK, m0, off); od = __shfl_xor_sync(FULLMASK, d0, off);
        nm = fmaxf(m0, om); d0 = d0 * __expf(m0 - nm) + od * __expf(om - nm); m0 = nm;
        om = __shfl_xor_sync(FULLMASK, m1, off); od = __shfl_xor_sync(FULLMASK, d1, off);
        nm = fmaxf(m1, om); d1 = d1 * __expf(m1 - nm) + od * __expf(om - nm); m1 = nm;
        om = __shfl_xor_sync(FULLMASK, m2, off); od = __shfl_xor_sync(FULLMASK, d2, off);
        nm = fmaxf(m2, om); d2 = d2 * __expf(m2 - nm) + od * __expf(om - nm); m2 = nm;
        om = __shfl_xor_sync(FULLMASK, m3, off); od = __shfl_xor_sync(FULLMASK, d3, off);
        nm = fmaxf(m3, om); d3 = d3 * __expf(m3 - nm) + od * __expf(om - nm); m3 = nm;
    }
    float r0 = 1.f / d0, r1 = 1.f / d1, r2 = 1.f / d2, r3 = 1.f / d3;

    // weighted accumulate: lane owns cols [4*lane, 4*lane+4) — ONE LDG.64/edge
    float acc0 = 0.f, acc1 = 0.f, acc2 = 0.f, acc3 = 0.f;
    int hsel = lane >> 3;                 // head index for this lane's cols
    int buf = 0;
    {
        int e = s0 + lane;
        if (e < s1) {
            int sl = g_srcs[e];
            float4 a = *(const float4*)&g_as1[sl * 4];
            sw[warpid][0][lane][0] = __expf(lrelu(a.x + ad.x) - m0) * r0;
            sw[warpid][0][lane][1] = __expf(lrelu(a.y + ad.y) - m1) * r1;
            sw[warpid][0][lane][2] = __expf(lrelu(a.z + ad.z) - m2) * r2;
            sw[warpid][0][lane][3] = __expf(lrelu(a.w + ad.w) - m3) * r3;
            ss[warpid][0][lane] = sl;
        }
    }
    __syncwarp();
    for (int base = s0; base < s1; base += 32) {
        int nb = base + 32;
        if (nb < s1) {
            int e = nb + lane;
            if (e < s1) {
                int sl = g_srcs[e];
                float4 a = *(const float4*)&g_as1[sl * 4];
                sw[warpid][buf ^ 1][lane][0] = __expf(lrelu(a.x + ad.x) - m0) * r0;
                sw[warpid][buf ^ 1][lane][1] = __expf(lrelu(a.y + ad.y) - m1) * r1;
                sw[warpid][buf ^ 1][lane][2] = __expf(lrelu(a.z + ad.z) - m2) * r2;
                sw[warpid][buf ^ 1][lane][3] = __expf(lrelu(a.w + ad.w) - m3) * r3;
                ss[warpid][buf ^ 1][lane] = sl;
            }
        }
        int cnt = min(32, s1 - base);
        #pragma unroll 4
        for (int j = 0; j < cnt; j++) {
            int s = ss[warpid][buf][j];
            float wsel = sw[warpid][buf][j][hsel];
            uint2 hraw = *(const uint2*)&g_h1h[s * 128 + lane * 4];
            float2 h01 = __half22float2(*(__half2*)&hraw.x);
            float2 h23 = __half22float2(*(__half2*)&hraw.y);
            acc0 = fmaf(h01.x, wsel, acc0);
            acc1 = fmaf(h01.y, wsel, acc1);
            acc2 = fmaf(h23.x, wsel, acc2);
            acc3 = fmaf(h23.y, wsel, acc3);
        }
        __syncwarp();
        buf ^= 1;
    }
    float4 bb = *(const float4*)&b1[lane * 4];
    *(float4*)&g_out1[n * 128 + lane * 4] =
        make_float4(fmaxf(acc0 + bb.x, 0.f), fmaxf(acc1 + bb.y, 0.f),
                    fmaxf(acc2 + bb.z, 0.f), fmaxf(acc3 + bb.w, 0.f));
}

// ---- GEMM2: h2 = out1 @ W2 (FFMA2) + fused alpha2 + fp16 mirror ------------
__global__ __launch_bounds__(256, 2) void gemm2_kernel(const float* __restrict__ W,
                                                       const float* __restrict__ a_src,
                                                       const float* __restrict__ a_dst,
                                                       int rowBase) {
    __shared__ __align__(16) float As[16][132];
    __shared__ __align__(16) float Bs[16][64];
    int tid = threadIdx.x;
    int tx = tid & 15, ty = tid >> 4;
    int blockRow = rowBase + blockIdx.x * 128;
    unsigned long long accp[8][2];
    #pragma unroll
    for (int i = 0; i < 8; i++) { accp[i][0] = 0ull; accp[i][1] = 0ull; }

    int id0 = tid * 2, id1 = tid * 2 + 1;
    int xr0 = id0 >> 2, xc0 = (id0 & 3) * 4;
    int xr1 = id1 >> 2, xc1 = (id1 & 3) * 4;
    int wr = tid >> 4, wc = (tid & 15) * 4;
    int grow0 = blockRow + xr0, grow1 = blockRow + xr1;

    float4 xa0 = make_float4(0, 0, 0, 0), xa1 = make_float4(0, 0, 0, 0);
    if (grow0 < N_NODES) xa0 = *(const float4*)&g_out1[grow0 * 128 + xc0];
    if (grow1 < N_NODES) xa1 = *(const float4*)&g_out1[grow1 * 128 + xc1];
    float4 wb = *(const float4*)&W[wr * 64 + wc];

    for (int k0 = 0; k0 < 128; k0 += 16) {
        As[xc0 + 0][xr0] = xa0.x; As[xc0 + 1][xr0] = xa0.y;
        As[xc0 + 2][xr0] = xa0.z; As[xc0 + 3][xr0] = xa0.w;
        As[xc1 + 0][xr1] = xa1.x; As[xc1 + 1][xr1] = xa1.y;
        As[xc1 + 2][xr1] = xa1.z; As[xc1 + 3][xr1] = xa1.w;
        *(float4*)&Bs[wr][wc] = wb;
        __syncthreads();
        if (k0 + 16 < 128) {
            int kn = k0 + 16;
            if (grow0 < N_NODES) xa0 = *(const float4*)&g_out1[grow0 * 128 + kn + xc0];
            if (grow1 < N_NODES) xa1 = *(const float4*)&g_out1[grow1 * 128 + kn + xc1];
            wb = *(const float4*)&W[(kn + wr) * 64 + wc];
        }
        #pragma unroll
        for (int k = 0; k < 16; k++) {
            float a[8];
            *(float4*)&a[0] = *(const float4*)&As[k][ty * 4];
            *(float4*)&a[4] = *(const float4*)&As[k][64 + ty * 4];
            unsigned long long bp[2];
            bp[0] = *(const unsigned long long*)&Bs[k][tx * 4];
            bp[1] = *(const unsigned long long*)&Bs[k][tx * 4 + 2];
            #pragma unroll
            for (int i = 0; i < 8; i++) {
                unsigned long long ap = pack_dup(a[i]);
                ffma2(accp[i][0], ap, bp[0]);
                ffma2(accp[i][1], ap, bp[1]);
            }
        }
        __syncthreads();
    }

    float as4[4], ad4[4];
    #pragma unroll
    for (int j = 0; j < 4; j++) {
        as4[j] = a_src[tx * 4 + j];
        ad4[j] = a_dst[tx * 4 + j];
    }
    #pragma unroll
    for (int i = 0; i < 8; i++) {
        int gr = blockRow + ((i < 4) ? (ty * 4 + i) : (64 + ty * 4 + i - 4));
        if (gr >= N_NODES) continue;
        float2 p0 = unpack2(accp[i][0]), p1 = unpack2(accp[i][1]);
        __half2 q0 = __floats2half2_rn(p0.x, p0.y);
        __half2 q1 = __floats2half2_rn(p1.x, p1.y);
        *(uint2*)&g_h2h[gr * 64 + tx * 4] = make_uint2(h2_bits(q0), h2_bits(q1));
        float ps = p0.x * as4[0] + p0.y * as4[1] + p1.x * as4[2] + p1.y * as4[3];
        float pd = p0.x * ad4[0] + p0.y * ad4[1] + p1.x * ad4[2] + p1.y * ad4[3];
        #pragma unroll
        for (int off = 1; off <= 8; off <<= 1) {
            ps += __shfl_xor_sync(FULLMASK, ps, off);
            pd += __shfl_xor_sync(FULLMASK, pd, off);
        }
        if (tx == 0) { g_as2[gr] = ps; g_ad2[gr] = pd; }
    }
}

// ---- layer-2 aggregation: warp per dst node; fp16 gather (1 LDG.32/edge) ---
__global__ __launch_bounds__(256) void agg2_kernel(const float* __restrict__ b2,
                                                   float* __restrict__ out) {
    __shared__ float sw[8][2][32];
    __shared__ int   ss[8][2][32];
    int warpid = threadIdx.x >> 5;
    int lane = threadIdx.x & 31;
    int n = blockIdx.x * 8 + warpid;
    if (n >= N_NODES) return;
    int s0 = g_rowstart[n], s1 = g_rowstart[n + 1];
    float ad = g_ad2[n];

    float m = -1e30f, d = 0.f;
    for (int e = s0 + lane; e < s1; e += 32) {
        float ev = lrelu(g_as2[g_srcs[e]] + ad);
        float nm = fmaxf(m, ev);
        d = d * __expf(m - nm) + __expf(ev - nm);
        m = nm;
    }
    #pragma unroll
    for (int off = 16; off >= 1; off >>= 1) {
        float om = __shfl_xor_sync(FULLMASK, m, off);
        float od = __shfl_xor_sync(FULLMASK, d, off);
        float nm = fmaxf(m, om);
        d = d * __expf(m - nm) + od * __expf(om - nm);
        m = nm;
    }
    float rd = 1.f / d;

    float acc0 = 0.f, acc1 = 0.f;
    int buf = 0;
    {
        int e = s0 + lane;
        if (e < s1) {
            int sl = g_srcs[e];
            sw[warpid][0][lane] = __expf(lrelu(g_as2[sl] + ad) - m) * rd;
            ss[warpid][0][lane] = sl;
        }
    }
    __syncwarp();
    for (int base = s0; base < s1; base += 32) {
        int nb = base + 32;
        if (nb < s1) {
            int e = nb + lane;
            if (e < s1) {
                int sl = g_srcs[e];
                sw[warpid][buf ^ 1][lane] = __expf(lrelu(g_as2[sl] + ad) - m) * rd;
                ss[warpid][buf ^ 1][lane] = sl;
            }
        }
        int cnt = min(32, s1 - base);
        #pragma unroll 4
        for (int j = 0; j < cnt; j++) {
            float wj = sw[warpid][buf][j];
            int s = ss[warpid][buf][j];
            uint32_t hraw = *(const uint32_t*)&g_h2h[s * 64 + lane * 2];
            float2 h = __half22float2(*(__half2*)&hraw);
            acc0 = fmaf(h.x, wj, acc0);
            acc1 = fmaf(h.y, wj, acc1);
        }
        __syncwarp();
        buf ^= 1;
    }
    float2 bb = *(const float2*)&b2[lane * 2];
    *(float2*)&out[n * 64 + lane * 2] = make_float2(acc0 + bb.x, acc1 + bb.y);
}

// ---------------- launcher ----------------
extern "C" void kernel_launch(void* const* d_in, const int* in_sizes, int n_in,
                              void* d_out, int out_size) {
    const float* x      = (const float*)d_in[0];
    const int*   ei     = (const int*)d_in[1];   // int32 (JAX x64 disabled)
    // d_in[2] edge_weight unused (PyG GATConv ignores it with edge_dim unset)
    const float* W1     = (const float*)d_in[3];
    const float* a_src1 = (const float*)d_in[4];
    const float* a_dst1 = (const float*)d_in[5];
    const float* b1     = (const float*)d_in[6];
    const float* W2     = (const float*)d_in[7];
    const float* a_src2 = (const float*)d_in[8];
    const float* a_dst2 = (const float*)d_in[9];
    const float* b2     = (const float*)d_in[10];
    float*       out    = (float*)d_out;

    static cudaStream_t s2 = nullptr;
    static cudaEvent_t evFork = nullptr, evJoin = nullptr, evA = nullptr, evG2a = nullptr;
    static void* degPtr = nullptr;
    if (s2 == nullptr) {
        cudaStreamCreateWithFlags(&s2, cudaStreamNonBlocking);
        cudaEventCreateWithFlags(&evFork, cudaEventDisableTiming);
        cudaEventCreateWithFlags(&evJoin, cudaEventDisableTiming);
        cudaEventCreateWithFlags(&evA, cudaEventDisableTiming);
        cudaEventCreateWithFlags(&evG2a, cudaEventDisableTiming);
        cudaGetSymbolAddress(&degPtr, g_deg);
    }

    // fork: CSR build on side stream, overlapped with GEMM1
    cudaEventRecord(evFork, 0);
    cudaStreamWaitEvent(s2, evFork, 0);
    cudaMemsetAsync(degPtr, 0, N_NODES * sizeof(int), s2);
    build_deg_kernel<<<(E_TOT / 4 + 255) / 256, 256, 0, s2>>>(ei);
    scan1_kernel<<<NBLK, 256, 0, s2>>>();
    scan2_kernel<<<1, 256, 0, s2>>>();
    scan3_kernel<<<NBLK, 256, 0, s2>>>();
    scatter_kernel<<<(E_TOT / 4 + 255) / 256, 256, 0, s2>>>(ei);
    cudaEventRecord(evJoin, s2);

    gemm1_kernel<<<(N_NODES + 127) / 128, 256>>>(x, W1, a_src1, a_dst1);

    // join: agg1 needs the CSR
    cudaStreamWaitEvent(0, evJoin, 0);

    // agg1 half A -> (side stream) gemm2 half A overlapped with agg1 half B
    agg1_kernel<<<N_HALF / 8, 256>>>(b1, 0, N_HALF);
    cudaEventRecord(evA, 0);
    agg1_kernel<<<(N_NODES - N_HALF + 7) / 8, 256>>>(b1, N_HALF, N_NODES - N_HALF);

    cudaStreamWaitEvent(s2, evA, 0);
    gemm2_kernel<<<N_HALF / 128, 256, 0, s2>>>(W2, a_src2, a_dst2, 0);
    cudaEventRecord(evG2a, s2);

    gemm2_kernel<<<(N_NODES - N_HALF + 127) / 128, 256>>>(W2, a_src2, a_dst2, N_HALF);

    // agg2 needs both gemm2 halves
    cudaStreamWaitEvent(0, evG2a, 0);
    agg2_kernel<<<(N_NODES + 7) / 8, 256>>>(b2, out);
}